// round 2
// baseline (speedup 1.0000x reference)
#include <cuda_runtime.h>
#include <cuda_bf16.h>
#include <math.h>
#include <float.h>
#include <stdint.h>

// ---------------------------------------------------------------------------
// Problem constants
// ---------------------------------------------------------------------------
#define NROI   1000
#define FH     38
#define FW     50
#define FC     512
#define CROP   14
#define POOL   7
#define DFLAT  (POOL*POOL*FC)   // 25088
#define DH     4096
#define NCLS   21
#define NREG   80

// ---------------------------------------------------------------------------
// Scratch (static device memory: allocation-free)
// ---------------------------------------------------------------------------
__device__ float g_pooled[NROI * DFLAT];   // ~100 MB
__device__ float g_h1[NROI * DH];
__device__ float g_h2[NROI * DH];
__device__ float g_cls[NROI * NCLS];

// ---------------------------------------------------------------------------
// Helpers
// ---------------------------------------------------------------------------
__device__ __forceinline__ uint32_t f2tf32(float x) {
    uint32_t u;
    asm("cvt.rna.tf32.f32 %0, %1;" : "=r"(u) : "f"(x));
    return u;
}

__device__ __forceinline__ void mma_tf32(float* d, const uint32_t* a, const uint32_t* b) {
    asm volatile(
        "mma.sync.aligned.m16n8k8.row.col.f32.tf32.tf32.f32 "
        "{%0,%1,%2,%3}, {%4,%5,%6,%7}, {%8,%9}, {%0,%1,%2,%3};\n"
        : "+f"(d[0]), "+f"(d[1]), "+f"(d[2]), "+f"(d[3])
        : "r"(a[0]), "r"(a[1]), "r"(a[2]), "r"(a[3]), "r"(b[0]), "r"(b[1]));
}

// ---------------------------------------------------------------------------
// Kernel 1: ROI crop_and_resize (14x14 bilinear) + 2x2 maxpool -> [N, 25088]
// One block per ROI; each thread handles 4 contiguous channels via float4.
// feats (3.9 MB) fits in L2, so corner gathers are L2 hits.
// ---------------------------------------------------------------------------
__global__ void roi_pool_kernel(const float* __restrict__ feats,
                                const float* __restrict__ boxes,
                                float* __restrict__ out) {
    int n = blockIdx.x;
    int tid = threadIdx.x;

    __shared__ int   y0s[CROP], y1s[CROP], x0s[CROP], x1s[CROP];
    __shared__ float wys[CROP], wxs[CROP];

    if (tid < CROP) {
        float y1 = boxes[n * 4 + 0];
        float y2 = boxes[n * 4 + 2];
        float v  = y1 * (float)(FH - 1) + (float)tid * ((y2 - y1) * (float)(FH - 1) / (float)(CROP - 1));
        float f  = floorf(v);
        int   i0 = (int)f;
        if (i0 < 0) i0 = 0;
        if (i0 > FH - 1) i0 = FH - 1;
        int i1 = i0 + 1;
        if (i1 > FH - 1) i1 = FH - 1;
        y0s[tid] = i0; y1s[tid] = i1; wys[tid] = v - f;
    } else if (tid < 2 * CROP) {
        int i = tid - CROP;
        float x1 = boxes[n * 4 + 1];
        float x2 = boxes[n * 4 + 3];
        float v  = x1 * (float)(FW - 1) + (float)i * ((x2 - x1) * (float)(FW - 1) / (float)(CROP - 1));
        float f  = floorf(v);
        int   i0 = (int)f;
        if (i0 < 0) i0 = 0;
        if (i0 > FW - 1) i0 = FW - 1;
        int i1 = i0 + 1;
        if (i1 > FW - 1) i1 = FW - 1;
        x0s[i] = i0; x1s[i] = i1; wxs[i] = v - f;
    }
    __syncthreads();

    // 4 channels per thread: idx over DFLAT/4 = 6272 vector elements
    for (int idx = tid; idx < DFLAT / 4; idx += blockDim.x) {
        int c4 = idx & (FC / 4 - 1);   // 0..127 -> channel = c4*4
        int p  = idx >> 7;             // 0..48
        int py = p / POOL;
        int px = p % POOL;

        float m0 = -FLT_MAX, m1 = -FLT_MAX, m2 = -FLT_MAX, m3 = -FLT_MAX;
        #pragma unroll
        for (int dy = 0; dy < 2; ++dy) {
            int   iy = 2 * py + dy;
            int   yA = y0s[iy], yB = y1s[iy];
            float wy = wys[iy];
            #pragma unroll
            for (int dx = 0; dx < 2; ++dx) {
                int   ix = 2 * px + dx;
                int   xA = x0s[ix], xB = x1s[ix];
                float wx = wxs[ix];
                float4 f00 = *(const float4*)&feats[((yA * FW + xA) * FC) + c4 * 4];
                float4 f01 = *(const float4*)&feats[((yA * FW + xB) * FC) + c4 * 4];
                float4 f10 = *(const float4*)&feats[((yB * FW + xA) * FC) + c4 * 4];
                float4 f11 = *(const float4*)&feats[((yB * FW + xB) * FC) + c4 * 4];
                float owx = 1.0f - wx, owy = 1.0f - wy;
                float t, b, v;
                t = f00.x * owx + f01.x * wx; b = f10.x * owx + f11.x * wx;
                v = t * owy + b * wy; m0 = fmaxf(m0, v);
                t = f00.y * owx + f01.y * wx; b = f10.y * owx + f11.y * wx;
                v = t * owy + b * wy; m1 = fmaxf(m1, v);
                t = f00.z * owx + f01.z * wx; b = f10.z * owx + f11.z * wx;
                v = t * owy + b * wy; m2 = fmaxf(m2, v);
                t = f00.w * owx + f01.w * wx; b = f10.w * owx + f11.w * wx;
                v = t * owy + b * wy; m3 = fmaxf(m3, v);
            }
        }
        float4 r; r.x = m0; r.y = m1; r.z = m2; r.w = m3;
        *(float4*)&out[(size_t)n * DFLAT + p * FC + c4 * 4] = r;
    }
}

// ---------------------------------------------------------------------------
// Kernel 2: TF32 tensor-core GEMM, D = relu(A @ B + bias)
// A: [M, K] row-major fp32, B: [K, N] row-major fp32.
// Tiles: 128x128x32, 8 warps (2x4), warp tile 64x32, mma m16n8k8.
// Double-buffered smem, register-staged global prefetch.
// ---------------------------------------------------------------------------
#define BM 128
#define BN 128
#define BK 32
#define ASTR 36
#define BSTR 132
#define AS_STAGE (BM * ASTR)   // 4608
#define BS_STAGE (BK * BSTR)   // 4224

__global__ __launch_bounds__(256, 1)
void gemm_tf32_relu(const float* __restrict__ A, const float* __restrict__ B,
                    const float* __restrict__ bias, float* __restrict__ D,
                    int M, int N, int K) {
    extern __shared__ float smem[];
    float* As = smem;                     // 2 stages [128][36]
    float* Bs = smem + 2 * AS_STAGE;      // 2 stages [32][132]

    const int tid    = threadIdx.x;
    const int bm     = blockIdx.y * BM;
    const int bn     = blockIdx.x * BN;
    const int warpId = tid >> 5;
    const int lane   = tid & 31;
    const int gid    = lane >> 2;   // group id 0..7
    const int tig    = lane & 3;    // thread in group
    const int warpM  = (warpId >> 2) * 64;
    const int warpN  = (warpId & 3) * 32;

    const int aRow0 = tid >> 3;          // 0..31 (4 passes of 32 rows)
    const int aCol  = (tid & 7) * 4;
    const int bRow0 = tid >> 5;          // 0..7  (4 passes of 8 rows)
    const int bCol  = (tid & 31) * 4;

    float acc[4][4][4];
    #pragma unroll
    for (int i = 0; i < 4; ++i)
        #pragma unroll
        for (int j = 0; j < 4; ++j)
            #pragma unroll
            for (int r = 0; r < 4; ++r) acc[i][j][r] = 0.0f;

    float4 aReg[4], bReg[4];
    const int T = K / BK;

    // ---- prologue: load tile 0 ----
    {
        const int kbase = 0;
        #pragma unroll
        for (int i = 0; i < 4; ++i) {
            int gm = bm + aRow0 + 32 * i;
            if (gm < M) aReg[i] = *(const float4*)(A + (size_t)gm * K + kbase + aCol);
            else        aReg[i] = make_float4(0.f, 0.f, 0.f, 0.f);
        }
        #pragma unroll
        for (int i = 0; i < 4; ++i) {
            int k = kbase + bRow0 + 8 * i;
            bReg[i] = *(const float4*)(B + (size_t)k * N + bn + bCol);
        }
        #pragma unroll
        for (int i = 0; i < 4; ++i) {
            int r = aRow0 + 32 * i;
            float* p = As + r * ASTR + aCol;
            p[0] = __uint_as_float(f2tf32(aReg[i].x));
            p[1] = __uint_as_float(f2tf32(aReg[i].y));
            p[2] = __uint_as_float(f2tf32(aReg[i].z));
            p[3] = __uint_as_float(f2tf32(aReg[i].w));
        }
        #pragma unroll
        for (int i = 0; i < 4; ++i) {
            int k = bRow0 + 8 * i;
            float* p = Bs + k * BSTR + bCol;
            p[0] = __uint_as_float(f2tf32(bReg[i].x));
            p[1] = __uint_as_float(f2tf32(bReg[i].y));
            p[2] = __uint_as_float(f2tf32(bReg[i].z));
            p[3] = __uint_as_float(f2tf32(bReg[i].w));
        }
    }
    __syncthreads();

    for (int kt = 0; kt < T; ++kt) {
        const int cur = kt & 1;

        if (kt + 1 < T) {
            const int kbase = (kt + 1) * BK;
            #pragma unroll
            for (int i = 0; i < 4; ++i) {
                int gm = bm + aRow0 + 32 * i;
                if (gm < M) aReg[i] = *(const float4*)(A + (size_t)gm * K + kbase + aCol);
                else        aReg[i] = make_float4(0.f, 0.f, 0.f, 0.f);
            }
            #pragma unroll
            for (int i = 0; i < 4; ++i) {
                int k = kbase + bRow0 + 8 * i;
                bReg[i] = *(const float4*)(B + (size_t)k * N + bn + bCol);
            }
        }

        // ---- compute current stage ----
        {
            const float* as = As + cur * AS_STAGE;
            const float* bs = Bs + cur * BS_STAGE;
            #pragma unroll
            for (int ks = 0; ks < 4; ++ks) {
                uint32_t af[4][4];
                uint32_t bf[4][2];
                #pragma unroll
                for (int mf = 0; mf < 4; ++mf) {
                    int r = warpM + mf * 16 + gid;
                    int c = ks * 8 + tig;
                    af[mf][0] = __float_as_uint(as[r * ASTR + c]);
                    af[mf][1] = __float_as_uint(as[(r + 8) * ASTR + c]);
                    af[mf][2] = __float_as_uint(as[r * ASTR + c + 4]);
                    af[mf][3] = __float_as_uint(as[(r + 8) * ASTR + c + 4]);
                }
                #pragma unroll
                for (int nf = 0; nf < 4; ++nf) {
                    int col = warpN + nf * 8 + gid;
                    int k   = ks * 8 + tig;
                    bf[nf][0] = __float_as_uint(bs[k * BSTR + col]);
                    bf[nf][1] = __float_as_uint(bs[(k + 4) * BSTR + col]);
                }
                #pragma unroll
                for (int mf = 0; mf < 4; ++mf)
                    #pragma unroll
                    for (int nf = 0; nf < 4; ++nf)
                        mma_tf32(acc[mf][nf], af[mf], bf[nf]);
            }
        }
        __syncthreads();

        if (kt + 1 < T) {
            float* as = As + (cur ^ 1) * AS_STAGE;
            float* bs = Bs + (cur ^ 1) * BS_STAGE;
            #pragma unroll
            for (int i = 0; i < 4; ++i) {
                int r = aRow0 + 32 * i;
                float* p = as + r * ASTR + aCol;
                p[0] = __uint_as_float(f2tf32(aReg[i].x));
                p[1] = __uint_as_float(f2tf32(aReg[i].y));
                p[2] = __uint_as_float(f2tf32(aReg[i].z));
                p[3] = __uint_as_float(f2tf32(aReg[i].w));
            }
            #pragma unroll
            for (int i = 0; i < 4; ++i) {
                int k = bRow0 + 8 * i;
                float* p = bs + k * BSTR + bCol;
                p[0] = __uint_as_float(f2tf32(bReg[i].x));
                p[1] = __uint_as_float(f2tf32(bReg[i].y));
                p[2] = __uint_as_float(f2tf32(bReg[i].z));
                p[3] = __uint_as_float(f2tf32(bReg[i].w));
            }
            __syncthreads();
        }
    }

    // ---- epilogue: bias + relu ----
    #pragma unroll
    for (int mf = 0; mf < 4; ++mf) {
        #pragma unroll
        for (int nf = 0; nf < 4; ++nf) {
            int row0 = bm + warpM + mf * 16 + gid;
            int col0 = bn + warpN + nf * 8 + tig * 2;
            float bv0 = bias[col0];
            float bv1 = bias[col0 + 1];
            if (row0 < M) {
                float v0 = acc[mf][nf][0] + bv0;
                float v1 = acc[mf][nf][1] + bv1;
                D[(size_t)row0 * N + col0]     = v0 > 0.f ? v0 : 0.f;
                D[(size_t)row0 * N + col0 + 1] = v1 > 0.f ? v1 : 0.f;
            }
            if (row0 + 8 < M) {
                float v2 = acc[mf][nf][2] + bv0;
                float v3 = acc[mf][nf][3] + bv1;
                D[(size_t)(row0 + 8) * N + col0]     = v2 > 0.f ? v2 : 0.f;
                D[(size_t)(row0 + 8) * N + col0 + 1] = v3 > 0.f ? v3 : 0.f;
            }
        }
    }
}

// ---------------------------------------------------------------------------
// Kernel 3: heads. logits = h2 @ [Wc | Wr] + [bc | br]
// ---------------------------------------------------------------------------
__global__ void heads_kernel(const float* __restrict__ X,
                             const float* __restrict__ Wc, const float* __restrict__ bc,
                             const float* __restrict__ Wr, const float* __restrict__ br,
                             float* __restrict__ cls_logits,
                             float* __restrict__ reg_out) {
    __shared__ float Xs[8 * 128];
    const int tid  = threadIdx.x;
    const int m0   = blockIdx.x * 8;
    const int nIdx = tid & 127;
    const int half = tid >> 7;           // 0 or 1
    const bool active = (nIdx < NCLS + NREG);

    float acc0 = 0.f, acc1 = 0.f, acc2 = 0.f, acc3 = 0.f;

    for (int kc = 0; kc < DH; kc += 128) {
        #pragma unroll
        for (int i = 0; i < 4; ++i) {
            int idx = tid + i * 256;
            int r = idx >> 7, c = idx & 127;
            int gm = m0 + r;
            Xs[idx] = (gm < NROI) ? X[(size_t)gm * DH + kc + c] : 0.f;
        }
        __syncthreads();

        #pragma unroll 4
        for (int kk = 0; kk < 128; kk += 4) {
            float w0 = 0.f, w1 = 0.f, w2 = 0.f, w3 = 0.f;
            if (active) {
                if (nIdx < NCLS) {
                    w0 = Wc[(size_t)(kc + kk + 0) * NCLS + nIdx];
                    w1 = Wc[(size_t)(kc + kk + 1) * NCLS + nIdx];
                    w2 = Wc[(size_t)(kc + kk + 2) * NCLS + nIdx];
                    w3 = Wc[(size_t)(kc + kk + 3) * NCLS + nIdx];
                } else {
                    int nr = nIdx - NCLS;
                    w0 = Wr[(size_t)(kc + kk + 0) * NREG + nr];
                    w1 = Wr[(size_t)(kc + kk + 1) * NREG + nr];
                    w2 = Wr[(size_t)(kc + kk + 2) * NREG + nr];
                    w3 = Wr[(size_t)(kc + kk + 3) * NREG + nr];
                }
            }
            {
                float4 x0 = *(const float4*)&Xs[(half * 4 + 0) * 128 + kk];
                float4 x1 = *(const float4*)&Xs[(half * 4 + 1) * 128 + kk];
                float4 x2 = *(const float4*)&Xs[(half * 4 + 2) * 128 + kk];
                float4 x3 = *(const float4*)&Xs[(half * 4 + 3) * 128 + kk];
                acc0 += x0.x * w0 + x0.y * w1 + x0.z * w2 + x0.w * w3;
                acc1 += x1.x * w0 + x1.y * w1 + x1.z * w2 + x1.w * w3;
                acc2 += x2.x * w0 + x2.y * w1 + x2.z * w2 + x2.w * w3;
                acc3 += x3.x * w0 + x3.y * w1 + x3.z * w2 + x3.w * w3;
            }
        }
        __syncthreads();
    }

    if (active) {
        float accs[4] = {acc0, acc1, acc2, acc3};
        #pragma unroll
        for (int j = 0; j < 4; ++j) {
            int m = m0 + half * 4 + j;
            if (m < NROI) {
                if (nIdx < NCLS) {
                    cls_logits[m * NCLS + nIdx] = accs[j] + bc[nIdx];
                } else {
                    int nr = nIdx - NCLS;
                    reg_out[m * NREG + nr] = accs[j] + br[nr];
                }
            }
        }
    }
}

// ---------------------------------------------------------------------------
// Kernel 4: softmax over 21 classes per ROI
// ---------------------------------------------------------------------------
__global__ void softmax21_kernel(const float* __restrict__ logits,
                                 float* __restrict__ out) {
    int m = blockIdx.x * blockDim.x + threadIdx.x;
    if (m >= NROI) return;
    float v[NCLS];
    float mx = -FLT_MAX;
    #pragma unroll
    for (int j = 0; j < NCLS; ++j) {
        v[j] = logits[m * NCLS + j];
        mx = fmaxf(mx, v[j]);
    }
    float s = 0.f;
    #pragma unroll
    for (int j = 0; j < NCLS; ++j) {
        v[j] = expf(v[j] - mx);
        s += v[j];
    }
    float inv = 1.0f / s;
    #pragma unroll
    for (int j = 0; j < NCLS; ++j) out[m * NCLS + j] = v[j] * inv;
}

// ---------------------------------------------------------------------------
// Launch
// ---------------------------------------------------------------------------
extern "C" void kernel_launch(void* const* d_in, const int* in_sizes, int n_in,
                              void* d_out, int out_size) {
    const float* feats = (const float*)d_in[0];
    const float* props = (const float*)d_in[1];
    const float* W1    = (const float*)d_in[2];
    const float* b1    = (const float*)d_in[3];
    const float* W2    = (const float*)d_in[4];
    const float* b2    = (const float*)d_in[5];
    const float* Wc    = (const float*)d_in[6];
    const float* bc    = (const float*)d_in[7];
    const float* Wr    = (const float*)d_in[8];
    const float* br    = (const float*)d_in[9];
    float* out = (float*)d_out;

    float *pooled, *h1, *h2, *cls;
    cudaGetSymbolAddress((void**)&pooled, g_pooled);
    cudaGetSymbolAddress((void**)&h1, g_h1);
    cudaGetSymbolAddress((void**)&h2, g_h2);
    cudaGetSymbolAddress((void**)&cls, g_cls);

    size_t smemsz = (size_t)(2 * AS_STAGE + 2 * BS_STAGE) * sizeof(float); // 70656 B
    cudaFuncSetAttribute(gemm_tf32_relu, cudaFuncAttributeMaxDynamicSharedMemorySize, (int)smemsz);

    roi_pool_kernel<<<NROI, 256>>>(feats, props, pooled);

    gemm_tf32_relu<<<dim3(DH / BN, (NROI + BM - 1) / BM), 256, smemsz>>>(
        pooled, W1, b1, h1, NROI, DH, DFLAT);

    gemm_tf32_relu<<<dim3(DH / BN, (NROI + BM - 1) / BM), 256, smemsz>>>(
        h1, W2, b2, h2, NROI, DH, DH);

    heads_kernel<<<(NROI + 7) / 8, 256>>>(h2, Wc, bc, Wr, br, cls, out + NROI * NCLS);

    softmax21_kernel<<<4, 256>>>(cls, out);
}

// round 3
// speedup vs baseline: 1.1514x; 1.1514x over previous
#include <cuda_runtime.h>
#include <cuda_bf16.h>
#include <math.h>
#include <float.h>
#include <stdint.h>

// ---------------------------------------------------------------------------
// Problem constants
// ---------------------------------------------------------------------------
#define NROI   1000
#define FH     38
#define FW     50
#define FC     512
#define CROP   14
#define POOL   7
#define DFLAT  (POOL*POOL*FC)   // 25088
#define DH     4096
#define NCLS   21
#define NREG   80
#define NOUT   (NCLS + NREG)    // 101
#define NPAD   104
#define NSPLIT 16
#define KCH    (DH / NSPLIT)    // 256

// ---------------------------------------------------------------------------
// Scratch (static device memory: allocation-free)
// ---------------------------------------------------------------------------
__device__ float g_pooled[NROI * DFLAT];   // ~100 MB
__device__ float g_h1[NROI * DH];
__device__ float g_h2[NROI * DH];
__device__ float g_cls[NROI * NCLS];
__device__ float g_part[NSPLIT * NROI * NPAD];  // 6.7 MB

// ---------------------------------------------------------------------------
// Helpers
// ---------------------------------------------------------------------------
__device__ __forceinline__ uint32_t f2tf32(float x) {
    uint32_t u;
    asm("cvt.rna.tf32.f32 %0, %1;" : "=r"(u) : "f"(x));
    return u;
}

__device__ __forceinline__ void mma_tf32(float* d, const uint32_t* a, const uint32_t* b) {
    asm volatile(
        "mma.sync.aligned.m16n8k8.row.col.f32.tf32.tf32.f32 "
        "{%0,%1,%2,%3}, {%4,%5,%6,%7}, {%8,%9}, {%0,%1,%2,%3};\n"
        : "+f"(d[0]), "+f"(d[1]), "+f"(d[2]), "+f"(d[3])
        : "r"(a[0]), "r"(a[1]), "r"(a[2]), "r"(a[3]), "r"(b[0]), "r"(b[1]));
}

// ---------------------------------------------------------------------------
// Kernel 1: ROI crop_and_resize (14x14 bilinear) + 2x2 maxpool -> [N, 25088]
// ---------------------------------------------------------------------------
__global__ void roi_pool_kernel(const float* __restrict__ feats,
                                const float* __restrict__ boxes,
                                float* __restrict__ out) {
    int n = blockIdx.x;
    int tid = threadIdx.x;

    __shared__ int   y0s[CROP], y1s[CROP], x0s[CROP], x1s[CROP];
    __shared__ float wys[CROP], wxs[CROP];

    if (tid < CROP) {
        float y1 = boxes[n * 4 + 0];
        float y2 = boxes[n * 4 + 2];
        float v  = y1 * (float)(FH - 1) + (float)tid * ((y2 - y1) * (float)(FH - 1) / (float)(CROP - 1));
        float f  = floorf(v);
        int   i0 = (int)f;
        if (i0 < 0) i0 = 0;
        if (i0 > FH - 1) i0 = FH - 1;
        int i1 = i0 + 1;
        if (i1 > FH - 1) i1 = FH - 1;
        y0s[tid] = i0; y1s[tid] = i1; wys[tid] = v - f;
    } else if (tid < 2 * CROP) {
        int i = tid - CROP;
        float x1 = boxes[n * 4 + 1];
        float x2 = boxes[n * 4 + 3];
        float v  = x1 * (float)(FW - 1) + (float)i * ((x2 - x1) * (float)(FW - 1) / (float)(CROP - 1));
        float f  = floorf(v);
        int   i0 = (int)f;
        if (i0 < 0) i0 = 0;
        if (i0 > FW - 1) i0 = FW - 1;
        int i1 = i0 + 1;
        if (i1 > FW - 1) i1 = FW - 1;
        x0s[i] = i0; x1s[i] = i1; wxs[i] = v - f;
    }
    __syncthreads();

    for (int idx = tid; idx < DFLAT / 4; idx += blockDim.x) {
        int c4 = idx & (FC / 4 - 1);
        int p  = idx >> 7;
        int py = p / POOL;
        int px = p % POOL;

        float m0 = -FLT_MAX, m1 = -FLT_MAX, m2 = -FLT_MAX, m3 = -FLT_MAX;
        #pragma unroll
        for (int dy = 0; dy < 2; ++dy) {
            int   iy = 2 * py + dy;
            int   yA = y0s[iy], yB = y1s[iy];
            float wy = wys[iy];
            #pragma unroll
            for (int dx = 0; dx < 2; ++dx) {
                int   ix = 2 * px + dx;
                int   xA = x0s[ix], xB = x1s[ix];
                float wx = wxs[ix];
                float4 f00 = *(const float4*)&feats[((yA * FW + xA) * FC) + c4 * 4];
                float4 f01 = *(const float4*)&feats[((yA * FW + xB) * FC) + c4 * 4];
                float4 f10 = *(const float4*)&feats[((yB * FW + xA) * FC) + c4 * 4];
                float4 f11 = *(const float4*)&feats[((yB * FW + xB) * FC) + c4 * 4];
                float owx = 1.0f - wx, owy = 1.0f - wy;
                float t, b, v;
                t = f00.x * owx + f01.x * wx; b = f10.x * owx + f11.x * wx;
                v = t * owy + b * wy; m0 = fmaxf(m0, v);
                t = f00.y * owx + f01.y * wx; b = f10.y * owx + f11.y * wx;
                v = t * owy + b * wy; m1 = fmaxf(m1, v);
                t = f00.z * owx + f01.z * wx; b = f10.z * owx + f11.z * wx;
                v = t * owy + b * wy; m2 = fmaxf(m2, v);
                t = f00.w * owx + f01.w * wx; b = f10.w * owx + f11.w * wx;
                v = t * owy + b * wy; m3 = fmaxf(m3, v);
            }
        }
        float4 r; r.x = m0; r.y = m1; r.z = m2; r.w = m3;
        *(float4*)&out[(size_t)n * DFLAT + p * FC + c4 * 4] = r;
    }
}

// ---------------------------------------------------------------------------
// Kernel 2: TF32 tensor-core GEMM, D = relu(A @ B + bias)
// ---------------------------------------------------------------------------
#define BM 128
#define BN 128
#define BK 32
#define ASTR 36
#define BSTR 132
#define AS_STAGE (BM * ASTR)
#define BS_STAGE (BK * BSTR)

__global__ __launch_bounds__(256, 1)
void gemm_tf32_relu(const float* __restrict__ A, const float* __restrict__ B,
                    const float* __restrict__ bias, float* __restrict__ D,
                    int M, int N, int K) {
    extern __shared__ float smem[];
    float* As = smem;
    float* Bs = smem + 2 * AS_STAGE;

    const int tid    = threadIdx.x;
    const int bm     = blockIdx.y * BM;
    const int bn     = blockIdx.x * BN;
    const int warpId = tid >> 5;
    const int lane   = tid & 31;
    const int gid    = lane >> 2;
    const int tig    = lane & 3;
    const int warpM  = (warpId >> 2) * 64;
    const int warpN  = (warpId & 3) * 32;

    const int aRow0 = tid >> 3;
    const int aCol  = (tid & 7) * 4;
    const int bRow0 = tid >> 5;
    const int bCol  = (tid & 31) * 4;

    float acc[4][4][4];
    #pragma unroll
    for (int i = 0; i < 4; ++i)
        #pragma unroll
        for (int j = 0; j < 4; ++j)
            #pragma unroll
            for (int r = 0; r < 4; ++r) acc[i][j][r] = 0.0f;

    float4 aReg[4], bReg[4];
    const int T = K / BK;

    {
        const int kbase = 0;
        #pragma unroll
        for (int i = 0; i < 4; ++i) {
            int gm = bm + aRow0 + 32 * i;
            if (gm < M) aReg[i] = *(const float4*)(A + (size_t)gm * K + kbase + aCol);
            else        aReg[i] = make_float4(0.f, 0.f, 0.f, 0.f);
        }
        #pragma unroll
        for (int i = 0; i < 4; ++i) {
            int k = kbase + bRow0 + 8 * i;
            bReg[i] = *(const float4*)(B + (size_t)k * N + bn + bCol);
        }
        #pragma unroll
        for (int i = 0; i < 4; ++i) {
            int r = aRow0 + 32 * i;
            float* p = As + r * ASTR + aCol;
            p[0] = __uint_as_float(f2tf32(aReg[i].x));
            p[1] = __uint_as_float(f2tf32(aReg[i].y));
            p[2] = __uint_as_float(f2tf32(aReg[i].z));
            p[3] = __uint_as_float(f2tf32(aReg[i].w));
        }
        #pragma unroll
        for (int i = 0; i < 4; ++i) {
            int k = bRow0 + 8 * i;
            float* p = Bs + k * BSTR + bCol;
            p[0] = __uint_as_float(f2tf32(bReg[i].x));
            p[1] = __uint_as_float(f2tf32(bReg[i].y));
            p[2] = __uint_as_float(f2tf32(bReg[i].z));
            p[3] = __uint_as_float(f2tf32(bReg[i].w));
        }
    }
    __syncthreads();

    for (int kt = 0; kt < T; ++kt) {
        const int cur = kt & 1;

        if (kt + 1 < T) {
            const int kbase = (kt + 1) * BK;
            #pragma unroll
            for (int i = 0; i < 4; ++i) {
                int gm = bm + aRow0 + 32 * i;
                if (gm < M) aReg[i] = *(const float4*)(A + (size_t)gm * K + kbase + aCol);
                else        aReg[i] = make_float4(0.f, 0.f, 0.f, 0.f);
            }
            #pragma unroll
            for (int i = 0; i < 4; ++i) {
                int k = kbase + bRow0 + 8 * i;
                bReg[i] = *(const float4*)(B + (size_t)k * N + bn + bCol);
            }
        }

        {
            const float* as = As + cur * AS_STAGE;
            const float* bs = Bs + cur * BS_STAGE;
            #pragma unroll
            for (int ks = 0; ks < 4; ++ks) {
                uint32_t af[4][4];
                uint32_t bf[4][2];
                #pragma unroll
                for (int mf = 0; mf < 4; ++mf) {
                    int r = warpM + mf * 16 + gid;
                    int c = ks * 8 + tig;
                    af[mf][0] = __float_as_uint(as[r * ASTR + c]);
                    af[mf][1] = __float_as_uint(as[(r + 8) * ASTR + c]);
                    af[mf][2] = __float_as_uint(as[r * ASTR + c + 4]);
                    af[mf][3] = __float_as_uint(as[(r + 8) * ASTR + c + 4]);
                }
                #pragma unroll
                for (int nf = 0; nf < 4; ++nf) {
                    int col = warpN + nf * 8 + gid;
                    int k   = ks * 8 + tig;
                    bf[nf][0] = __float_as_uint(bs[k * BSTR + col]);
                    bf[nf][1] = __float_as_uint(bs[(k + 4) * BSTR + col]);
                }
                #pragma unroll
                for (int mf = 0; mf < 4; ++mf)
                    #pragma unroll
                    for (int nf = 0; nf < 4; ++nf)
                        mma_tf32(acc[mf][nf], af[mf], bf[nf]);
            }
        }
        __syncthreads();

        if (kt + 1 < T) {
            float* as = As + (cur ^ 1) * AS_STAGE;
            float* bs = Bs + (cur ^ 1) * BS_STAGE;
            #pragma unroll
            for (int i = 0; i < 4; ++i) {
                int r = aRow0 + 32 * i;
                float* p = as + r * ASTR + aCol;
                p[0] = __uint_as_float(f2tf32(aReg[i].x));
                p[1] = __uint_as_float(f2tf32(aReg[i].y));
                p[2] = __uint_as_float(f2tf32(aReg[i].z));
                p[3] = __uint_as_float(f2tf32(aReg[i].w));
            }
            #pragma unroll
            for (int i = 0; i < 4; ++i) {
                int k = bRow0 + 8 * i;
                float* p = bs + k * BSTR + bCol;
                p[0] = __uint_as_float(f2tf32(bReg[i].x));
                p[1] = __uint_as_float(f2tf32(bReg[i].y));
                p[2] = __uint_as_float(f2tf32(bReg[i].z));
                p[3] = __uint_as_float(f2tf32(bReg[i].w));
            }
            __syncthreads();
        }
    }

    #pragma unroll
    for (int mf = 0; mf < 4; ++mf) {
        #pragma unroll
        for (int nf = 0; nf < 4; ++nf) {
            int row0 = bm + warpM + mf * 16 + gid;
            int col0 = bn + warpN + nf * 8 + tig * 2;
            float bv0 = bias[col0];
            float bv1 = bias[col0 + 1];
            if (row0 < M) {
                float v0 = acc[mf][nf][0] + bv0;
                float v1 = acc[mf][nf][1] + bv1;
                D[(size_t)row0 * N + col0]     = v0 > 0.f ? v0 : 0.f;
                D[(size_t)row0 * N + col0 + 1] = v1 > 0.f ? v1 : 0.f;
            }
            if (row0 + 8 < M) {
                float v2 = acc[mf][nf][2] + bv0;
                float v3 = acc[mf][nf][3] + bv1;
                D[(size_t)(row0 + 8) * N + col0]     = v2 > 0.f ? v2 : 0.f;
                D[(size_t)(row0 + 8) * N + col0 + 1] = v3 > 0.f ? v3 : 0.f;
            }
        }
    }
}

// ---------------------------------------------------------------------------
// Kernel 3a: heads split-K partial sums.
// grid (125, NSPLIT): blockIdx.x = 8-ROI tile, blockIdx.y = K chunk of 256.
// Each thread: one output col (101 active of 128) x 4 ROIs.
// Writes partial[ks][m][NPAD].
// ---------------------------------------------------------------------------
__global__ void heads_partial_kernel(const float* __restrict__ X,
                                     const float* __restrict__ Wc,
                                     const float* __restrict__ Wr,
                                     float* __restrict__ part) {
    __shared__ float Xs[8 * 128];
    const int tid   = threadIdx.x;
    const int m0    = blockIdx.x * 8;
    const int ks    = blockIdx.y;
    const int kbase = ks * KCH;
    const int nIdx  = tid & 127;
    const int half  = tid >> 7;
    const bool active = (nIdx < NOUT);

    float acc0 = 0.f, acc1 = 0.f, acc2 = 0.f, acc3 = 0.f;

    for (int kc = kbase; kc < kbase + KCH; kc += 128) {
        #pragma unroll
        for (int i = 0; i < 4; ++i) {
            int idx = tid + i * 256;
            int r = idx >> 7, c = idx & 127;
            Xs[idx] = X[(size_t)(m0 + r) * DH + kc + c];
        }
        __syncthreads();

        #pragma unroll 4
        for (int kk = 0; kk < 128; kk += 4) {
            float w0 = 0.f, w1 = 0.f, w2 = 0.f, w3 = 0.f;
            if (active) {
                if (nIdx < NCLS) {
                    w0 = Wc[(size_t)(kc + kk + 0) * NCLS + nIdx];
                    w1 = Wc[(size_t)(kc + kk + 1) * NCLS + nIdx];
                    w2 = Wc[(size_t)(kc + kk + 2) * NCLS + nIdx];
                    w3 = Wc[(size_t)(kc + kk + 3) * NCLS + nIdx];
                } else {
                    int nr = nIdx - NCLS;
                    w0 = Wr[(size_t)(kc + kk + 0) * NREG + nr];
                    w1 = Wr[(size_t)(kc + kk + 1) * NREG + nr];
                    w2 = Wr[(size_t)(kc + kk + 2) * NREG + nr];
                    w3 = Wr[(size_t)(kc + kk + 3) * NREG + nr];
                }
            }
            {
                float4 x0 = *(const float4*)&Xs[(half * 4 + 0) * 128 + kk];
                float4 x1 = *(const float4*)&Xs[(half * 4 + 1) * 128 + kk];
                float4 x2 = *(const float4*)&Xs[(half * 4 + 2) * 128 + kk];
                float4 x3 = *(const float4*)&Xs[(half * 4 + 3) * 128 + kk];
                acc0 += x0.x * w0 + x0.y * w1 + x0.z * w2 + x0.w * w3;
                acc1 += x1.x * w0 + x1.y * w1 + x1.z * w2 + x1.w * w3;
                acc2 += x2.x * w0 + x2.y * w1 + x2.z * w2 + x2.w * w3;
                acc3 += x3.x * w0 + x3.y * w1 + x3.z * w2 + x3.w * w3;
            }
        }
        __syncthreads();
    }

    if (active) {
        float accs[4] = {acc0, acc1, acc2, acc3};
        #pragma unroll
        for (int j = 0; j < 4; ++j) {
            int m = m0 + half * 4 + j;
            part[((size_t)ks * NROI + m) * NPAD + nIdx] = accs[j];
        }
    }
}

// ---------------------------------------------------------------------------
// Kernel 3b: reduce partials + bias, scatter to cls logits / reg output.
// ---------------------------------------------------------------------------
__global__ void heads_reduce_kernel(const float* __restrict__ part,
                                    const float* __restrict__ bc,
                                    const float* __restrict__ br,
                                    float* __restrict__ cls_logits,
                                    float* __restrict__ reg_out) {
    int idx = blockIdx.x * blockDim.x + threadIdx.x;
    if (idx >= NROI * NPAD) return;
    int m = idx / NPAD;
    int n = idx % NPAD;
    if (n >= NOUT) return;

    float s = 0.f;
    #pragma unroll
    for (int ks = 0; ks < NSPLIT; ++ks)
        s += part[((size_t)ks * NROI + m) * NPAD + n];

    if (n < NCLS) cls_logits[m * NCLS + n] = s + bc[n];
    else          reg_out[m * NREG + (n - NCLS)] = s + br[n - NCLS];
}

// ---------------------------------------------------------------------------
// Kernel 4: softmax over 21 classes per ROI
// ---------------------------------------------------------------------------
__global__ void softmax21_kernel(const float* __restrict__ logits,
                                 float* __restrict__ out) {
    int m = blockIdx.x * blockDim.x + threadIdx.x;
    if (m >= NROI) return;
    float v[NCLS];
    float mx = -FLT_MAX;
    #pragma unroll
    for (int j = 0; j < NCLS; ++j) {
        v[j] = logits[m * NCLS + j];
        mx = fmaxf(mx, v[j]);
    }
    float s = 0.f;
    #pragma unroll
    for (int j = 0; j < NCLS; ++j) {
        v[j] = expf(v[j] - mx);
        s += v[j];
    }
    float inv = 1.0f / s;
    #pragma unroll
    for (int j = 0; j < NCLS; ++j) out[m * NCLS + j] = v[j] * inv;
}

// ---------------------------------------------------------------------------
// Launch
// ---------------------------------------------------------------------------
extern "C" void kernel_launch(void* const* d_in, const int* in_sizes, int n_in,
                              void* d_out, int out_size) {
    const float* feats = (const float*)d_in[0];
    const float* props = (const float*)d_in[1];
    const float* W1    = (const float*)d_in[2];
    const float* b1    = (const float*)d_in[3];
    const float* W2    = (const float*)d_in[4];
    const float* b2    = (const float*)d_in[5];
    const float* Wc    = (const float*)d_in[6];
    const float* bc    = (const float*)d_in[7];
    const float* Wr    = (const float*)d_in[8];
    const float* br    = (const float*)d_in[9];
    float* out = (float*)d_out;

    float *pooled, *h1, *h2, *cls, *part;
    cudaGetSymbolAddress((void**)&pooled, g_pooled);
    cudaGetSymbolAddress((void**)&h1, g_h1);
    cudaGetSymbolAddress((void**)&h2, g_h2);
    cudaGetSymbolAddress((void**)&cls, g_cls);
    cudaGetSymbolAddress((void**)&part, g_part);

    size_t smemsz = (size_t)(2 * AS_STAGE + 2 * BS_STAGE) * sizeof(float); // 70656 B
    cudaFuncSetAttribute(gemm_tf32_relu, cudaFuncAttributeMaxDynamicSharedMemorySize, (int)smemsz);

    roi_pool_kernel<<<NROI, 256>>>(feats, props, pooled);

    gemm_tf32_relu<<<dim3(DH / BN, (NROI + BM - 1) / BM), 256, smemsz>>>(
        pooled, W1, b1, h1, NROI, DH, DFLAT);

    gemm_tf32_relu<<<dim3(DH / BN, (NROI + BM - 1) / BM), 256, smemsz>>>(
        h1, W2, b2, h2, NROI, DH, DH);

    heads_partial_kernel<<<dim3(NROI / 8, NSPLIT), 256>>>(h2, Wc, Wr, part);

    heads_reduce_kernel<<<(NROI * NPAD + 255) / 256, 256>>>(
        part, bc, br, cls, out + NROI * NCLS);

    softmax21_kernel<<<4, 256>>>(cls, out);
}

// round 5
// speedup vs baseline: 1.4726x; 1.2790x over previous
#include <cuda_runtime.h>
#include <cuda_bf16.h>
#include <math.h>
#include <float.h>
#include <stdint.h>

// ---------------------------------------------------------------------------
// Problem constants
// ---------------------------------------------------------------------------
#define NROI   1000
#define FH     38
#define FW     50
#define FC     512
#define CROP   14
#define POOL   7
#define DFLAT  (POOL*POOL*FC)   // 25088
#define DH     4096
#define NCLS   21
#define NREG   80
#define NOUT   (NCLS + NREG)    // 101
#define NPAD   104
#define NSPLIT 16
#define KCH    (DH / NSPLIT)    // 256

// ---------------------------------------------------------------------------
// Scratch (static device memory: allocation-free)
// ---------------------------------------------------------------------------
__device__ float g_pooled[(size_t)NROI * DFLAT];
__device__ float g_h1[(size_t)NROI * DH];
__device__ float g_h2[(size_t)NROI * DH];
__device__ float g_cls[NROI * NCLS];
__device__ float g_part[NSPLIT * NROI * NPAD];

// ---------------------------------------------------------------------------
// Helpers
// ---------------------------------------------------------------------------
__device__ __forceinline__ uint32_t f2tf32(float x) {
    uint32_t u;
    asm("cvt.rna.tf32.f32 %0, %1;" : "=r"(u) : "f"(x));
    return u;
}

__device__ __forceinline__ void mma_tf32(float* d, const uint32_t* a, const uint32_t* b) {
    asm volatile(
        "mma.sync.aligned.m16n8k8.row.col.f32.tf32.tf32.f32 "
        "{%0,%1,%2,%3}, {%4,%5,%6,%7}, {%8,%9}, {%0,%1,%2,%3};\n"
        : "+f"(d[0]), "+f"(d[1]), "+f"(d[2]), "+f"(d[3])
        : "r"(a[0]), "r"(a[1]), "r"(a[2]), "r"(a[3]), "r"(b[0]), "r"(b[1]));
}

__device__ __forceinline__ uint32_t smem_u32(const void* p) {
    uint32_t a;
    asm("{ .reg .u64 t; cvta.to.shared.u64 t, %1; cvt.u32.u64 %0, t; }"
        : "=r"(a) : "l"(p));
    return a;
}

__device__ __forceinline__ void cpasync16(uint32_t dst, const void* src) {
    asm volatile("cp.async.cg.shared.global [%0], [%1], 16;"
                 :: "r"(dst), "l"(src) : "memory");
}

// ---------------------------------------------------------------------------
// Kernel 1: ROI crop_and_resize + 2x2 maxpool -> [N, 25088], tf32-rounded fp32
// ---------------------------------------------------------------------------
__global__ void roi_pool_kernel(const float* __restrict__ feats,
                                const float* __restrict__ boxes,
                                float* __restrict__ out) {
    int n = blockIdx.x;
    int tid = threadIdx.x;

    __shared__ int   y0s[CROP], y1s[CROP], x0s[CROP], x1s[CROP];
    __shared__ float wys[CROP], wxs[CROP];

    if (tid < CROP) {
        float y1 = boxes[n * 4 + 0];
        float y2 = boxes[n * 4 + 2];
        float v  = y1 * (float)(FH - 1) + (float)tid * ((y2 - y1) * (float)(FH - 1) / (float)(CROP - 1));
        float f  = floorf(v);
        int   i0 = (int)f;
        if (i0 < 0) i0 = 0;
        if (i0 > FH - 1) i0 = FH - 1;
        int i1 = i0 + 1;
        if (i1 > FH - 1) i1 = FH - 1;
        y0s[tid] = i0; y1s[tid] = i1; wys[tid] = v - f;
    } else if (tid < 2 * CROP) {
        int i = tid - CROP;
        float x1 = boxes[n * 4 + 1];
        float x2 = boxes[n * 4 + 3];
        float v  = x1 * (float)(FW - 1) + (float)i * ((x2 - x1) * (float)(FW - 1) / (float)(CROP - 1));
        float f  = floorf(v);
        int   i0 = (int)f;
        if (i0 < 0) i0 = 0;
        if (i0 > FW - 1) i0 = FW - 1;
        int i1 = i0 + 1;
        if (i1 > FW - 1) i1 = FW - 1;
        x0s[i] = i0; x1s[i] = i1; wxs[i] = v - f;
    }
    __syncthreads();

    for (int idx = tid; idx < DFLAT / 4; idx += blockDim.x) {
        int c4 = idx & (FC / 4 - 1);
        int p  = idx >> 7;
        int py = p / POOL;
        int px = p % POOL;

        float m[4] = {-FLT_MAX, -FLT_MAX, -FLT_MAX, -FLT_MAX};
        #pragma unroll
        for (int dy = 0; dy < 2; ++dy) {
            int   iy = 2 * py + dy;
            int   yA = y0s[iy], yB = y1s[iy];
            float wy = wys[iy];
            #pragma unroll
            for (int dx = 0; dx < 2; ++dx) {
                int   ix = 2 * px + dx;
                int   xA = x0s[ix], xB = x1s[ix];
                float wx = wxs[ix];
                float4 f00 = *(const float4*)&feats[((yA * FW + xA) * FC) + c4 * 4];
                float4 f01 = *(const float4*)&feats[((yA * FW + xB) * FC) + c4 * 4];
                float4 f10 = *(const float4*)&feats[((yB * FW + xA) * FC) + c4 * 4];
                float4 f11 = *(const float4*)&feats[((yB * FW + xB) * FC) + c4 * 4];
                float owx = 1.0f - wx, owy = 1.0f - wy;
                float t, b, v;
                t = f00.x * owx + f01.x * wx; b = f10.x * owx + f11.x * wx;
                v = t * owy + b * wy; m[0] = fmaxf(m[0], v);
                t = f00.y * owx + f01.y * wx; b = f10.y * owx + f11.y * wx;
                v = t * owy + b * wy; m[1] = fmaxf(m[1], v);
                t = f00.z * owx + f01.z * wx; b = f10.z * owx + f11.z * wx;
                v = t * owy + b * wy; m[2] = fmaxf(m[2], v);
                t = f00.w * owx + f01.w * wx; b = f10.w * owx + f11.w * wx;
                v = t * owy + b * wy; m[3] = fmaxf(m[3], v);
            }
        }
        float4 r;
        r.x = __uint_as_float(f2tf32(m[0]));
        r.y = __uint_as_float(f2tf32(m[1]));
        r.z = __uint_as_float(f2tf32(m[2]));
        r.w = __uint_as_float(f2tf32(m[3]));
        *(float4*)&out[(size_t)n * DFLAT + p * FC + c4 * 4] = r;
    }
}

// ---------------------------------------------------------------------------
// Kernel 2: TF32 GEMM, cp.async 3-stage pipeline, one sync per K-iter.
// D = relu(A @ B + bias). A [M,K] tf32-pre-rounded; B [K,N] raw fp32
// (rounded at fragment load). Tiles 128x128x32, 8 warps, warp tile 64x32.
// ---------------------------------------------------------------------------
#define BM 128
#define BN 128
#define BK 32
#define ASTR 36
#define BSTR 132
#define AS_FLOATS (BM * ASTR)             // 4608
#define BS_FLOATS (BK * BSTR)             // 4224
#define STAGE_FLOATS (AS_FLOATS + BS_FLOATS)  // 8832
#define NSTAGE 3

__device__ __forceinline__ void gemm_load_tile(
    uint32_t sbase, int slot, int kt, int tid,
    const float* __restrict__ A, const float* __restrict__ B,
    int bm, int bn, int M, int N, int K) {
    uint32_t sa = sbase + (uint32_t)slot * (STAGE_FLOATS * 4);
    uint32_t sbB = sa + AS_FLOATS * 4;
    int kb = kt * BK;
    #pragma unroll
    for (int i = 0; i < 4; ++i) {
        int c = tid + i * 256;          // 0..1023
        int r = c >> 3, kc = c & 7;     // row 0..127, 16B chunk 0..7
        int gm = bm + r;
        if (gm >= M) gm = 0;            // pad rows read row 0 (finite garbage)
        cpasync16(sa + (uint32_t)(r * ASTR + kc * 4) * 4,
                  A + (size_t)gm * K + kb + kc * 4);
    }
    #pragma unroll
    for (int i = 0; i < 4; ++i) {
        int c = tid + i * 256;
        int k = c >> 5, col = c & 31;   // k 0..31, 16B chunk 0..31
        cpasync16(sbB + (uint32_t)(k * BSTR + col * 4) * 4,
                  B + (size_t)(kb + k) * N + bn + col * 4);
    }
}

__global__ __launch_bounds__(256, 2)
void gemm_tf32_pipe(const float* __restrict__ A, const float* __restrict__ B,
                    const float* __restrict__ bias, float* __restrict__ D,
                    int M, int N, int K, int roundOut) {
    extern __shared__ float smem[];
    uint32_t sbase = smem_u32(smem);

    const int tid    = threadIdx.x;
    const int bm     = blockIdx.x * BM;   // M fast -> consecutive CTAs share B
    const int bn     = blockIdx.y * BN;
    const int warpId = tid >> 5;
    const int lane   = tid & 31;
    const int gid    = lane >> 2;
    const int tig    = lane & 3;
    const int warpM  = (warpId >> 2) * 64;
    const int warpN  = (warpId & 3) * 32;

    float acc[4][4][4];
    #pragma unroll
    for (int i = 0; i < 4; ++i)
        #pragma unroll
        for (int j = 0; j < 4; ++j)
            #pragma unroll
            for (int r = 0; r < 4; ++r) acc[i][j][r] = 0.0f;

    const int T = K / BK;

    // prologue: tiles 0, 1
    gemm_load_tile(sbase, 0, 0, tid, A, B, bm, bn, M, N, K);
    asm volatile("cp.async.commit_group;" ::: "memory");
    gemm_load_tile(sbase, 1, 1, tid, A, B, bm, bn, M, N, K);
    asm volatile("cp.async.commit_group;" ::: "memory");

    for (int kt = 0; kt < T; ++kt) {
        asm volatile("cp.async.wait_group 1;" ::: "memory");
        __syncthreads();

        // load tile kt+2 into slot (kt+2)%3 == slot of kt-1 (freed by sync)
        if (kt + 2 < T) {
            gemm_load_tile(sbase, (kt + 2) % NSTAGE, kt + 2, tid, A, B, bm, bn, M, N, K);
        }
        asm volatile("cp.async.commit_group;" ::: "memory");  // may be empty

        const float* as = smem + (size_t)(kt % NSTAGE) * STAGE_FLOATS;
        const float* bs = as + AS_FLOATS;
        #pragma unroll
        for (int ks = 0; ks < 4; ++ks) {
            uint32_t af[4][4];
            uint32_t bf[4][2];
            #pragma unroll
            for (int mf = 0; mf < 4; ++mf) {
                int r = warpM + mf * 16 + gid;
                int c = ks * 8 + tig;
                af[mf][0] = __float_as_uint(as[r * ASTR + c]);
                af[mf][1] = __float_as_uint(as[(r + 8) * ASTR + c]);
                af[mf][2] = __float_as_uint(as[r * ASTR + c + 4]);
                af[mf][3] = __float_as_uint(as[(r + 8) * ASTR + c + 4]);
            }
            #pragma unroll
            for (int nf = 0; nf < 4; ++nf) {
                int col = warpN + nf * 8 + gid;
                int k   = ks * 8 + tig;
                bf[nf][0] = f2tf32(bs[k * BSTR + col]);
                bf[nf][1] = f2tf32(bs[(k + 4) * BSTR + col]);
            }
            #pragma unroll
            for (int mf = 0; mf < 4; ++mf)
                #pragma unroll
                for (int nf = 0; nf < 4; ++nf)
                    mma_tf32(acc[mf][nf], af[mf], bf[nf]);
        }
    }

    // ---- epilogue: bias + relu (+ optional tf32 rounding for next GEMM) ----
    #pragma unroll
    for (int mf = 0; mf < 4; ++mf) {
        #pragma unroll
        for (int nf = 0; nf < 4; ++nf) {
            int row0 = bm + warpM + mf * 16 + gid;
            int col0 = bn + warpN + nf * 8 + tig * 2;
            float bv0 = bias[col0];
            float bv1 = bias[col0 + 1];
            if (row0 < M) {
                float v0 = fmaxf(acc[mf][nf][0] + bv0, 0.f);
                float v1 = fmaxf(acc[mf][nf][1] + bv1, 0.f);
                if (roundOut) {
                    v0 = __uint_as_float(f2tf32(v0));
                    v1 = __uint_as_float(f2tf32(v1));
                }
                D[(size_t)row0 * N + col0]     = v0;
                D[(size_t)row0 * N + col0 + 1] = v1;
            }
            if (row0 + 8 < M) {
                float v2 = fmaxf(acc[mf][nf][2] + bv0, 0.f);
                float v3 = fmaxf(acc[mf][nf][3] + bv1, 0.f);
                if (roundOut) {
                    v2 = __uint_as_float(f2tf32(v2));
                    v3 = __uint_as_float(f2tf32(v3));
                }
                D[(size_t)(row0 + 8) * N + col0]     = v2;
                D[(size_t)(row0 + 8) * N + col0 + 1] = v3;
            }
        }
    }
}

// ---------------------------------------------------------------------------
// Kernel 3a: heads split-K partial sums.
// ---------------------------------------------------------------------------
__global__ void heads_partial_kernel(const float* __restrict__ X,
                                     const float* __restrict__ Wc,
                                     const float* __restrict__ Wr,
                                     float* __restrict__ part) {
    __shared__ float Xs[8 * 128];
    const int tid   = threadIdx.x;
    const int m0    = blockIdx.x * 8;
    const int ks    = blockIdx.y;
    const int kbase = ks * KCH;
    const int nIdx  = tid & 127;
    const int half  = tid >> 7;
    const bool active = (nIdx < NOUT);

    float acc0 = 0.f, acc1 = 0.f, acc2 = 0.f, acc3 = 0.f;

    for (int kc = kbase; kc < kbase + KCH; kc += 128) {
        #pragma unroll
        for (int i = 0; i < 4; ++i) {
            int idx = tid + i * 256;
            int r = idx >> 7, c = idx & 127;
            Xs[idx] = X[(size_t)(m0 + r) * DH + kc + c];
        }
        __syncthreads();

        #pragma unroll 4
        for (int kk = 0; kk < 128; kk += 4) {
            float w0 = 0.f, w1 = 0.f, w2 = 0.f, w3 = 0.f;
            if (active) {
                if (nIdx < NCLS) {
                    w0 = Wc[(size_t)(kc + kk + 0) * NCLS + nIdx];
                    w1 = Wc[(size_t)(kc + kk + 1) * NCLS + nIdx];
                    w2 = Wc[(size_t)(kc + kk + 2) * NCLS + nIdx];
                    w3 = Wc[(size_t)(kc + kk + 3) * NCLS + nIdx];
                } else {
                    int nr = nIdx - NCLS;
                    w0 = Wr[(size_t)(kc + kk + 0) * NREG + nr];
                    w1 = Wr[(size_t)(kc + kk + 1) * NREG + nr];
                    w2 = Wr[(size_t)(kc + kk + 2) * NREG + nr];
                    w3 = Wr[(size_t)(kc + kk + 3) * NREG + nr];
                }
            }
            {
                float4 x0 = *(const float4*)&Xs[(half * 4 + 0) * 128 + kk];
                float4 x1 = *(const float4*)&Xs[(half * 4 + 1) * 128 + kk];
                float4 x2 = *(const float4*)&Xs[(half * 4 + 2) * 128 + kk];
                float4 x3 = *(const float4*)&Xs[(half * 4 + 3) * 128 + kk];
                acc0 += x0.x * w0 + x0.y * w1 + x0.z * w2 + x0.w * w3;
                acc1 += x1.x * w0 + x1.y * w1 + x1.z * w2 + x1.w * w3;
                acc2 += x2.x * w0 + x2.y * w1 + x2.z * w2 + x2.w * w3;
                acc3 += x3.x * w0 + x3.y * w1 + x3.z * w2 + x3.w * w3;
            }
        }
        __syncthreads();
    }

    if (active) {
        float accs[4] = {acc0, acc1, acc2, acc3};
        #pragma unroll
        for (int j = 0; j < 4; ++j) {
            int m = m0 + half * 4 + j;
            part[((size_t)ks * NROI + m) * NPAD + nIdx] = accs[j];
        }
    }
}

// ---------------------------------------------------------------------------
// Kernel 3b: reduce partials + bias
// ---------------------------------------------------------------------------
__global__ void heads_reduce_kernel(const float* __restrict__ part,
                                    const float* __restrict__ bc,
                                    const float* __restrict__ br,
                                    float* __restrict__ cls_logits,
                                    float* __restrict__ reg_out) {
    int idx = blockIdx.x * blockDim.x + threadIdx.x;
    if (idx >= NROI * NPAD) return;
    int m = idx / NPAD;
    int n = idx % NPAD;
    if (n >= NOUT) return;

    float s = 0.f;
    #pragma unroll
    for (int ks = 0; ks < NSPLIT; ++ks)
        s += part[((size_t)ks * NROI + m) * NPAD + n];

    if (n < NCLS) cls_logits[m * NCLS + n] = s + bc[n];
    else          reg_out[m * NREG + (n - NCLS)] = s + br[n - NCLS];
}

// ---------------------------------------------------------------------------
// Kernel 4: softmax over 21 classes
// ---------------------------------------------------------------------------
__global__ void softmax21_kernel(const float* __restrict__ logits,
                                 float* __restrict__ out) {
    int m = blockIdx.x * blockDim.x + threadIdx.x;
    if (m >= NROI) return;
    float v[NCLS];
    float mx = -FLT_MAX;
    #pragma unroll
    for (int j = 0; j < NCLS; ++j) {
        v[j] = logits[m * NCLS + j];
        mx = fmaxf(mx, v[j]);
    }
    float s = 0.f;
    #pragma unroll
    for (int j = 0; j < NCLS; ++j) {
        v[j] = expf(v[j] - mx);
        s += v[j];
    }
    float inv = 1.0f / s;
    #pragma unroll
    for (int j = 0; j < NCLS; ++j) out[m * NCLS + j] = v[j] * inv;
}

// ---------------------------------------------------------------------------
// Launch
// ---------------------------------------------------------------------------
extern "C" void kernel_launch(void* const* d_in, const int* in_sizes, int n_in,
                              void* d_out, int out_size) {
    const float* feats = (const float*)d_in[0];
    const float* props = (const float*)d_in[1];
    const float* W1    = (const float*)d_in[2];
    const float* b1    = (const float*)d_in[3];
    const float* W2    = (const float*)d_in[4];
    const float* b2    = (const float*)d_in[5];
    const float* Wc    = (const float*)d_in[6];
    const float* bc    = (const float*)d_in[7];
    const float* Wr    = (const float*)d_in[8];
    const float* br    = (const float*)d_in[9];
    float* out = (float*)d_out;

    float *pooled, *h1, *h2, *cls, *part;
    cudaGetSymbolAddress((void**)&pooled, g_pooled);
    cudaGetSymbolAddress((void**)&h1, g_h1);
    cudaGetSymbolAddress((void**)&h2, g_h2);
    cudaGetSymbolAddress((void**)&cls, g_cls);
    cudaGetSymbolAddress((void**)&part, g_part);

    const int smemsz = NSTAGE * STAGE_FLOATS * 4;  // 105984 B
    cudaFuncSetAttribute(gemm_tf32_pipe, cudaFuncAttributeMaxDynamicSharedMemorySize, smemsz);

    roi_pool_kernel<<<NROI, 256>>>(feats, props, pooled);

    // grid: x = M tiles (fast) so concurrent CTAs share the B (weight) stream
    gemm_tf32_pipe<<<dim3((NROI + BM - 1) / BM, DH / BN), 256, smemsz>>>(
        pooled, W1, b1, h1, NROI, DH, DFLAT, /*roundOut=*/1);

    gemm_tf32_pipe<<<dim3((NROI + BM - 1) / BM, DH / BN), 256, smemsz>>>(
        h1, W2, b2, h2, NROI, DH, DH, /*roundOut=*/0);

    heads_partial_kernel<<<dim3(NROI / 8, NSPLIT), 256>>>(h2, Wc, Wr, part);

    heads_reduce_kernel<<<(NROI * NPAD + 255) / 256, 256>>>(
        part, bc, br, cls, out + NROI * NCLS);

    softmax21_kernel<<<4, 256>>>(cls, out);
}

// round 8
// speedup vs baseline: 2.1356x; 1.4502x over previous
#include <cuda_runtime.h>
#include <cuda_fp16.h>
#include <math.h>
#include <float.h>
#include <stdint.h>

// ---------------------------------------------------------------------------
// Problem constants
// ---------------------------------------------------------------------------
#define NROI   1000
#define FH     38
#define FW     50
#define FC     512
#define CROP   14
#define POOL   7
#define DFLAT  (POOL*POOL*FC)   // 25088
#define DH     4096
#define NCLS   21
#define NREG   80
#define NOUT   (NCLS + NREG)    // 101
#define NPAD   104
#define NSPLIT 32
#define KCH    (DH / NSPLIT)    // 128

// ---------------------------------------------------------------------------
// Scratch (static device memory: allocation-free)
// ---------------------------------------------------------------------------
__device__ __half g_pooled[(size_t)NROI * DFLAT];
__device__ __half g_h1[(size_t)NROI * DH];
__device__ float  g_h2[(size_t)NROI * DH];
__device__ float  g_cls[NROI * NCLS];
__device__ float  g_part[NSPLIT * NROI * NPAD];

// ---------------------------------------------------------------------------
// Helpers
// ---------------------------------------------------------------------------
__device__ __forceinline__ void mma_f16(float* d, const uint32_t* a, const uint32_t* b) {
    asm volatile(
        "mma.sync.aligned.m16n8k16.row.col.f32.f16.f16.f32 "
        "{%0,%1,%2,%3}, {%4,%5,%6,%7}, {%8,%9}, {%0,%1,%2,%3};\n"
        : "+f"(d[0]), "+f"(d[1]), "+f"(d[2]), "+f"(d[3])
        : "r"(a[0]), "r"(a[1]), "r"(a[2]), "r"(a[3]), "r"(b[0]), "r"(b[1]));
}

__device__ __forceinline__ uint32_t smem_u32(const void* p) {
    uint32_t a;
    asm("{ .reg .u64 t; cvta.to.shared.u64 t, %1; cvt.u32.u64 %0, t; }"
        : "=r"(a) : "l"(p));
    return a;
}

__device__ __forceinline__ void cpasync16(uint32_t dst, const void* src) {
    asm volatile("cp.async.cg.shared.global [%0], [%1], 16;"
                 :: "r"(dst), "l"(src) : "memory");
}

__device__ __forceinline__ uint32_t pack_h2(float lo, float hi) {
    __half2 h = __floats2half2_rn(lo, hi);   // .x = lo (k even), .y = hi
    return *(uint32_t*)&h;
}

// ---------------------------------------------------------------------------
// Kernel 1: ROI crop_and_resize + 2x2 maxpool -> fp16 [N, 25088]
// ---------------------------------------------------------------------------
__global__ void roi_pool_kernel(const float* __restrict__ feats,
                                const float* __restrict__ boxes,
                                __half* __restrict__ out) {
    int n = blockIdx.x;
    int tid = threadIdx.x;

    __shared__ int   y0s[CROP], y1s[CROP], x0s[CROP], x1s[CROP];
    __shared__ float wys[CROP], wxs[CROP];

    if (tid < CROP) {
        float y1 = boxes[n * 4 + 0];
        float y2 = boxes[n * 4 + 2];
        float v  = y1 * (float)(FH - 1) + (float)tid * ((y2 - y1) * (float)(FH - 1) / (float)(CROP - 1));
        float f  = floorf(v);
        int   i0 = (int)f;
        if (i0 < 0) i0 = 0;
        if (i0 > FH - 1) i0 = FH - 1;
        int i1 = i0 + 1;
        if (i1 > FH - 1) i1 = FH - 1;
        y0s[tid] = i0; y1s[tid] = i1; wys[tid] = v - f;
    } else if (tid < 2 * CROP) {
        int i = tid - CROP;
        float x1 = boxes[n * 4 + 1];
        float x2 = boxes[n * 4 + 3];
        float v  = x1 * (float)(FW - 1) + (float)i * ((x2 - x1) * (float)(FW - 1) / (float)(CROP - 1));
        float f  = floorf(v);
        int   i0 = (int)f;
        if (i0 < 0) i0 = 0;
        if (i0 > FW - 1) i0 = FW - 1;
        int i1 = i0 + 1;
        if (i1 > FW - 1) i1 = FW - 1;
        x0s[i] = i0; x1s[i] = i1; wxs[i] = v - f;
    }
    __syncthreads();

    for (int idx = tid; idx < DFLAT / 4; idx += blockDim.x) {
        int c4 = idx & (FC / 4 - 1);
        int p  = idx >> 7;
        int py = p / POOL;
        int px = p % POOL;

        float m[4] = {-FLT_MAX, -FLT_MAX, -FLT_MAX, -FLT_MAX};
        #pragma unroll
        for (int dy = 0; dy < 2; ++dy) {
            int   iy = 2 * py + dy;
            int   yA = y0s[iy], yB = y1s[iy];
            float wy = wys[iy];
            #pragma unroll
            for (int dx = 0; dx < 2; ++dx) {
                int   ix = 2 * px + dx;
                int   xA = x0s[ix], xB = x1s[ix];
                float wx = wxs[ix];
                float4 f00 = *(const float4*)&feats[((yA * FW + xA) * FC) + c4 * 4];
                float4 f01 = *(const float4*)&feats[((yA * FW + xB) * FC) + c4 * 4];
                float4 f10 = *(const float4*)&feats[((yB * FW + xA) * FC) + c4 * 4];
                float4 f11 = *(const float4*)&feats[((yB * FW + xB) * FC) + c4 * 4];
                float owx = 1.0f - wx, owy = 1.0f - wy;
                float t, b, v;
                t = f00.x * owx + f01.x * wx; b = f10.x * owx + f11.x * wx;
                v = t * owy + b * wy; m[0] = fmaxf(m[0], v);
                t = f00.y * owx + f01.y * wx; b = f10.y * owx + f11.y * wx;
                v = t * owy + b * wy; m[1] = fmaxf(m[1], v);
                t = f00.z * owx + f01.z * wx; b = f10.z * owx + f11.z * wx;
                v = t * owy + b * wy; m[2] = fmaxf(m[2], v);
                t = f00.w * owx + f01.w * wx; b = f10.w * owx + f11.w * wx;
                v = t * owy + b * wy; m[3] = fmaxf(m[3], v);
            }
        }
        uint2 r;
        r.x = pack_h2(m[0], m[1]);
        r.y = pack_h2(m[2], m[3]);
        *(uint2*)&out[(size_t)n * DFLAT + p * FC + c4 * 4] = r;
    }
}

// ---------------------------------------------------------------------------
// Kernel 2: FP16 HMMA GEMM, cp.async 3-stage pipeline, one sync per K-iter.
// D = relu(A @ B + bias). A [M,K] fp16; B [K,N] fp32 (packed to fp16 at
// fragment load). Tiles 128x128x32, 8 warps, warp tile 64x32, mma m16n8k16.
// ---------------------------------------------------------------------------
#define BM 128
#define BN 128
#define BK 32
#define ASTR_H 40                         // halfs per A row (32 + 8 pad)
#define BSTR 132
#define A_BYTES (BM * ASTR_H * 2)         // 10240
#define B_BYTES (BK * BSTR * 4)           // 16896
#define STAGE_BYTES (A_BYTES + B_BYTES)   // 27136
#define NSTAGE 3

__device__ __forceinline__ void gemm_load_tile(
    uint32_t sbase, int slot, int kt, int tid,
    const __half* __restrict__ A, const float* __restrict__ B,
    int bm, int bn, int M, int N, int K) {
    uint32_t sa = sbase + (uint32_t)slot * STAGE_BYTES;
    uint32_t sbB = sa + A_BYTES;
    int kb = kt * BK;
    // A: 128 rows x 32 halfs = 512 chunks of 16B
    #pragma unroll
    for (int i = 0; i < 2; ++i) {
        int c = tid + i * 256;          // 0..511
        int r = c >> 2, ch = c & 3;
        int gm = bm + r;
        if (gm >= M) gm = 0;            // pad rows read row 0; discarded later
        cpasync16(sa + (uint32_t)(r * ASTR_H + ch * 8) * 2,
                  A + (size_t)gm * K + kb + ch * 8);
    }
    // B: 32 k-rows x 128 cols fp32 = 1024 chunks of 16B
    #pragma unroll
    for (int i = 0; i < 4; ++i) {
        int c = tid + i * 256;
        int k = c >> 5, col4 = c & 31;
        cpasync16(sbB + (uint32_t)(k * BSTR + col4 * 4) * 4,
                  B + (size_t)(kb + k) * N + bn + col4 * 4);
    }
}

__global__ __launch_bounds__(256, 2)
void gemm_f16_pipe(const __half* __restrict__ A, const float* __restrict__ B,
                   const float* __restrict__ bias,
                   __half* __restrict__ outH, float* __restrict__ outF,
                   int M, int N, int K) {
    extern __shared__ char smem[];
    uint32_t sbase = smem_u32(smem);

    const int tid    = threadIdx.x;
    const int bm     = blockIdx.x * BM;   // M fast -> concurrent CTAs share B
    const int bn     = blockIdx.y * BN;
    const int warpId = tid >> 5;
    const int lane   = tid & 31;
    const int gid    = lane >> 2;
    const int tig    = lane & 3;
    const int warpM  = (warpId >> 2) * 64;
    const int warpN  = (warpId & 3) * 32;

    float acc[4][4][4];
    #pragma unroll
    for (int i = 0; i < 4; ++i)
        #pragma unroll
        for (int j = 0; j < 4; ++j)
            #pragma unroll
            for (int r = 0; r < 4; ++r) acc[i][j][r] = 0.0f;

    const int T = K / BK;

    gemm_load_tile(sbase, 0, 0, tid, A, B, bm, bn, M, N, K);
    asm volatile("cp.async.commit_group;" ::: "memory");
    gemm_load_tile(sbase, 1, 1, tid, A, B, bm, bn, M, N, K);
    asm volatile("cp.async.commit_group;" ::: "memory");

    for (int kt = 0; kt < T; ++kt) {
        asm volatile("cp.async.wait_group 1;" ::: "memory");
        __syncthreads();

        if (kt + 2 < T) {
            gemm_load_tile(sbase, (kt + 2) % NSTAGE, kt + 2, tid, A, B, bm, bn, M, N, K);
        }
        asm volatile("cp.async.commit_group;" ::: "memory");  // may be empty

        const char*  stg = smem + (size_t)(kt % NSTAGE) * STAGE_BYTES;
        const __half* as = (const __half*)stg;
        const float*  bs = (const float*)(stg + A_BYTES);

        #pragma unroll
        for (int ks = 0; ks < 2; ++ks) {
            const int kk = ks * 16;
            uint32_t af[4][4];
            uint32_t bf[4][2];
            #pragma unroll
            for (int mf = 0; mf < 4; ++mf) {
                int r = warpM + mf * 16 + gid;
                const __half* ap = as + r * ASTR_H + kk + 2 * tig;
                af[mf][0] = *(const uint32_t*)(ap);                      // A[r][kk+2t..+1]
                af[mf][1] = *(const uint32_t*)(ap + 8 * ASTR_H);         // A[r+8][..]
                af[mf][2] = *(const uint32_t*)(ap + 8);                  // A[r][kk+2t+8..9]
                af[mf][3] = *(const uint32_t*)(ap + 8 * ASTR_H + 8);     // A[r+8][..+8]
            }
            #pragma unroll
            for (int nf = 0; nf < 4; ++nf) {
                int col = warpN + nf * 8 + gid;
                const float* bp = bs + (kk + 2 * tig) * BSTR + col;
                bf[nf][0] = pack_h2(bp[0],        bp[BSTR]);             // B[kk+2t], B[kk+2t+1]
                bf[nf][1] = pack_h2(bp[8 * BSTR], bp[9 * BSTR]);         // B[kk+2t+8], +9
            }
            #pragma unroll
            for (int mf = 0; mf < 4; ++mf)
                #pragma unroll
                for (int nf = 0; nf < 4; ++nf)
                    mma_f16(acc[mf][nf], af[mf], bf[nf]);
        }
    }

    // ---- epilogue: bias + relu; store fp16 (GEMM1) or fp32 (GEMM2) ----
    #pragma unroll
    for (int mf = 0; mf < 4; ++mf) {
        #pragma unroll
        for (int nf = 0; nf < 4; ++nf) {
            int row0 = bm + warpM + mf * 16 + gid;
            int col0 = bn + warpN + nf * 8 + tig * 2;
            float bv0 = bias[col0];
            float bv1 = bias[col0 + 1];
            if (row0 < M) {
                float v0 = fmaxf(acc[mf][nf][0] + bv0, 0.f);
                float v1 = fmaxf(acc[mf][nf][1] + bv1, 0.f);
                if (outH) *(uint32_t*)&outH[(size_t)row0 * N + col0] = pack_h2(v0, v1);
                else {
                    outF[(size_t)row0 * N + col0]     = v0;
                    outF[(size_t)row0 * N + col0 + 1] = v1;
                }
            }
            if (row0 + 8 < M) {
                float v2 = fmaxf(acc[mf][nf][2] + bv0, 0.f);
                float v3 = fmaxf(acc[mf][nf][3] + bv1, 0.f);
                if (outH) *(uint32_t*)&outH[(size_t)(row0 + 8) * N + col0] = pack_h2(v2, v3);
                else {
                    outF[(size_t)(row0 + 8) * N + col0]     = v2;
                    outF[(size_t)(row0 + 8) * N + col0 + 1] = v3;
                }
            }
        }
    }
}

// ---------------------------------------------------------------------------
// Kernel 3a: heads split-K partial sums (NSPLIT=32, KCH=128).
// ---------------------------------------------------------------------------
__global__ void heads_partial_kernel(const float* __restrict__ X,
                                     const float* __restrict__ Wc,
                                     const float* __restrict__ Wr,
                                     float* __restrict__ part) {
    __shared__ float Xs[8 * 128];
    const int tid   = threadIdx.x;
    const int m0    = blockIdx.x * 8;
    const int ks    = blockIdx.y;
    const int kbase = ks * KCH;
    const int nIdx  = tid & 127;
    const int half  = tid >> 7;
    const bool active = (nIdx < NOUT);

    float acc0 = 0.f, acc1 = 0.f, acc2 = 0.f, acc3 = 0.f;

    for (int kc = kbase; kc < kbase + KCH; kc += 128) {
        #pragma unroll
        for (int i = 0; i < 4; ++i) {
            int idx = tid + i * 256;
            int r = idx >> 7, c = idx & 127;
            Xs[idx] = X[(size_t)(m0 + r) * DH + kc + c];
        }
        __syncthreads();

        #pragma unroll 4
        for (int kk = 0; kk < 128; kk += 4) {
            float w0 = 0.f, w1 = 0.f, w2 = 0.f, w3 = 0.f;
            if (active) {
                if (nIdx < NCLS) {
                    w0 = Wc[(size_t)(kc + kk + 0) * NCLS + nIdx];
                    w1 = Wc[(size_t)(kc + kk + 1) * NCLS + nIdx];
                    w2 = Wc[(size_t)(kc + kk + 2) * NCLS + nIdx];
                    w3 = Wc[(size_t)(kc + kk + 3) * NCLS + nIdx];
                } else {
                    int nr = nIdx - NCLS;
                    w0 = Wr[(size_t)(kc + kk + 0) * NREG + nr];
                    w1 = Wr[(size_t)(kc + kk + 1) * NREG + nr];
                    w2 = Wr[(size_t)(kc + kk + 2) * NREG + nr];
                    w3 = Wr[(size_t)(kc + kk + 3) * NREG + nr];
                }
            }
            {
                float4 x0 = *(const float4*)&Xs[(half * 4 + 0) * 128 + kk];
                float4 x1 = *(const float4*)&Xs[(half * 4 + 1) * 128 + kk];
                float4 x2 = *(const float4*)&Xs[(half * 4 + 2) * 128 + kk];
                float4 x3 = *(const float4*)&Xs[(half * 4 + 3) * 128 + kk];
                acc0 += x0.x * w0 + x0.y * w1 + x0.z * w2 + x0.w * w3;
                acc1 += x1.x * w0 + x1.y * w1 + x1.z * w2 + x1.w * w3;
                acc2 += x2.x * w0 + x2.y * w1 + x2.z * w2 + x2.w * w3;
                acc3 += x3.x * w0 + x3.y * w1 + x3.z * w2 + x3.w * w3;
            }
        }
        __syncthreads();
    }

    if (active) {
        float accs[4] = {acc0, acc1, acc2, acc3};
        #pragma unroll
        for (int j = 0; j < 4; ++j) {
            int m = m0 + half * 4 + j;
            part[((size_t)ks * NROI + m) * NPAD + nIdx] = accs[j];
        }
    }
}

// ---------------------------------------------------------------------------
// Kernel 3b: reduce partials + bias
// ---------------------------------------------------------------------------
__global__ void heads_reduce_kernel(const float* __restrict__ part,
                                    const float* __restrict__ bc,
                                    const float* __restrict__ br,
                                    float* __restrict__ cls_logits,
                                    float* __restrict__ reg_out) {
    int idx = blockIdx.x * blockDim.x + threadIdx.x;
    if (idx >= NROI * NPAD) return;
    int m = idx / NPAD;
    int n = idx % NPAD;
    if (n >= NOUT) return;

    float s = 0.f;
    #pragma unroll
    for (int ks = 0; ks < NSPLIT; ++ks)
        s += part[((size_t)ks * NROI + m) * NPAD + n];

    if (n < NCLS) cls_logits[m * NCLS + n] = s + bc[n];
    else          reg_out[m * NREG + (n - NCLS)] = s + br[n - NCLS];
}

// ---------------------------------------------------------------------------
// Kernel 4: softmax over 21 classes
// ---------------------------------------------------------------------------
__global__ void softmax21_kernel(const float* __restrict__ logits,
                                 float* __restrict__ out) {
    int m = blockIdx.x * blockDim.x + threadIdx.x;
    if (m >= NROI) return;
    float v[NCLS];
    float mx = -FLT_MAX;
    #pragma unroll
    for (int j = 0; j < NCLS; ++j) {
        v[j] = logits[m * NCLS + j];
        mx = fmaxf(mx, v[j]);
    }
    float s = 0.f;
    #pragma unroll
    for (int j = 0; j < NCLS; ++j) {
        v[j] = expf(v[j] - mx);
        s += v[j];
    }
    float inv = 1.0f / s;
    #pragma unroll
    for (int j = 0; j < NCLS; ++j) out[m * NCLS + j] = v[j] * inv;
}

// ---------------------------------------------------------------------------
// Launch
// ---------------------------------------------------------------------------
extern "C" void kernel_launch(void* const* d_in, const int* in_sizes, int n_in,
                              void* d_out, int out_size) {
    const float* feats = (const float*)d_in[0];
    const float* props = (const float*)d_in[1];
    const float* W1    = (const float*)d_in[2];
    const float* b1    = (const float*)d_in[3];
    const float* W2    = (const float*)d_in[4];
    const float* b2    = (const float*)d_in[5];
    const float* Wc    = (const float*)d_in[6];
    const float* bc    = (const float*)d_in[7];
    const float* Wr    = (const float*)d_in[8];
    const float* br    = (const float*)d_in[9];
    float* out = (float*)d_out;

    __half *pooled, *h1;
    float *h2, *cls, *part;
    cudaGetSymbolAddress((void**)&pooled, g_pooled);
    cudaGetSymbolAddress((void**)&h1, g_h1);
    cudaGetSymbolAddress((void**)&h2, g_h2);
    cudaGetSymbolAddress((void**)&cls, g_cls);
    cudaGetSymbolAddress((void**)&part, g_part);

    const int smemsz = NSTAGE * STAGE_BYTES;  // 81408 B
    cudaFuncSetAttribute(gemm_f16_pipe, cudaFuncAttributeMaxDynamicSharedMemorySize, smemsz);

    roi_pool_kernel<<<NROI, 256>>>(feats, props, pooled);

    gemm_f16_pipe<<<dim3((NROI + BM - 1) / BM, DH / BN), 256, smemsz>>>(
        pooled, W1, b1, h1, (float*)0, NROI, DH, DFLAT);

    gemm_f16_pipe<<<dim3((NROI + BM - 1) / BM, DH / BN), 256, smemsz>>>(
        h1, W2, b2, (__half*)0, h2, NROI, DH, DH);

    heads_partial_kernel<<<dim3(NROI / 8, NSPLIT), 256>>>(h2, Wc, Wr, part);

    heads_reduce_kernel<<<(NROI * NPAD + 255) / 256, 256>>>(
        part, bc, br, cls, out + NROI * NCLS);

    softmax21_kernel<<<4, 256>>>(cls, out);
}

// round 10
// speedup vs baseline: 2.5225x; 1.1812x over previous
#include <cuda_runtime.h>
#include <cuda_fp16.h>
#include <math.h>
#include <float.h>
#include <stdint.h>

// ---------------------------------------------------------------------------
// Problem constants
// ---------------------------------------------------------------------------
#define NROI   1000
#define FH     38
#define FW     50
#define FC     512
#define CROP   14
#define POOL   7
#define DFLAT  (POOL*POOL*FC)   // 25088
#define DH     4096
#define NCLS   21
#define NREG   80
#define NOUT   (NCLS + NREG)    // 101
#define NPAD   104
#define NSPLIT 32
#define KCH    (DH / NSPLIT)    // 128

// ---------------------------------------------------------------------------
// Scratch (static device memory: allocation-free)
// ---------------------------------------------------------------------------
__device__ __half g_pooled[(size_t)NROI * DFLAT];
__device__ __half g_W1t[(size_t)DH * DFLAT];    // W1 transposed [N,K] fp16
__device__ __half g_W2t[(size_t)DH * DH];       // W2 transposed [N,K] fp16
__device__ __half g_h1[(size_t)NROI * DH];
__device__ float  g_h2[(size_t)NROI * DH];
__device__ float  g_cls[NROI * NCLS];
__device__ float  g_part[NSPLIT * NROI * NPAD];

// ---------------------------------------------------------------------------
// Helpers
// ---------------------------------------------------------------------------
__device__ __forceinline__ void mma_f16(float* d, const uint32_t* a, const uint32_t* b) {
    asm volatile(
        "mma.sync.aligned.m16n8k16.row.col.f32.f16.f16.f32 "
        "{%0,%1,%2,%3}, {%4,%5,%6,%7}, {%8,%9}, {%0,%1,%2,%3};\n"
        : "+f"(d[0]), "+f"(d[1]), "+f"(d[2]), "+f"(d[3])
        : "r"(a[0]), "r"(a[1]), "r"(a[2]), "r"(a[3]), "r"(b[0]), "r"(b[1]));
}

__device__ __forceinline__ void ldsm_x4(uint32_t* r, uint32_t addr) {
    asm volatile(
        "ldmatrix.sync.aligned.m8n8.x4.shared.b16 {%0,%1,%2,%3}, [%4];"
        : "=r"(r[0]), "=r"(r[1]), "=r"(r[2]), "=r"(r[3]) : "r"(addr));
}

__device__ __forceinline__ uint32_t smem_u32(const void* p) {
    uint32_t a;
    asm("{ .reg .u64 t; cvta.to.shared.u64 t, %1; cvt.u32.u64 %0, t; }"
        : "=r"(a) : "l"(p));
    return a;
}

__device__ __forceinline__ void cpasync16(uint32_t dst, const void* src) {
    asm volatile("cp.async.cg.shared.global [%0], [%1], 16;"
                 :: "r"(dst), "l"(src) : "memory");
}

__device__ __forceinline__ uint32_t pack_h2(float lo, float hi) {
    __half2 h = __floats2half2_rn(lo, hi);
    return *(uint32_t*)&h;
}

// ---------------------------------------------------------------------------
// Kernel 0: transpose + convert W[K,N] fp32 -> Wt[N,K] fp16
// ---------------------------------------------------------------------------
__global__ void transpose_f16_kernel(const float* __restrict__ W,
                                     __half* __restrict__ Wt,
                                     int K, int N) {
    __shared__ float s[32][33];
    int n0 = blockIdx.x * 32, k0 = blockIdx.y * 32;
    int tx = threadIdx.x, ty = threadIdx.y;
    #pragma unroll
    for (int i = ty; i < 32; i += 8)
        s[i][tx] = W[(size_t)(k0 + i) * N + n0 + tx];
    __syncthreads();
    #pragma unroll
    for (int i = ty; i < 32; i += 8)
        Wt[(size_t)(n0 + i) * K + k0 + tx] = __float2half(s[tx][i]);
}

// ---------------------------------------------------------------------------
// Kernel 1: ROI crop_and_resize + 2x2 maxpool -> fp16 [N, 25088]
// ---------------------------------------------------------------------------
__global__ void roi_pool_kernel(const float* __restrict__ feats,
                                const float* __restrict__ boxes,
                                __half* __restrict__ out) {
    int n = blockIdx.x;
    int tid = threadIdx.x;

    __shared__ int   y0s[CROP], y1s[CROP], x0s[CROP], x1s[CROP];
    __shared__ float wys[CROP], wxs[CROP];

    if (tid < CROP) {
        float y1 = boxes[n * 4 + 0];
        float y2 = boxes[n * 4 + 2];
        float v  = y1 * (float)(FH - 1) + (float)tid * ((y2 - y1) * (float)(FH - 1) / (float)(CROP - 1));
        float f  = floorf(v);
        int   i0 = (int)f;
        if (i0 < 0) i0 = 0;
        if (i0 > FH - 1) i0 = FH - 1;
        int i1 = i0 + 1;
        if (i1 > FH - 1) i1 = FH - 1;
        y0s[tid] = i0; y1s[tid] = i1; wys[tid] = v - f;
    } else if (tid < 2 * CROP) {
        int i = tid - CROP;
        float x1 = boxes[n * 4 + 1];
        float x2 = boxes[n * 4 + 3];
        float v  = x1 * (float)(FW - 1) + (float)i * ((x2 - x1) * (float)(FW - 1) / (float)(CROP - 1));
        float f  = floorf(v);
        int   i0 = (int)f;
        if (i0 < 0) i0 = 0;
        if (i0 > FW - 1) i0 = FW - 1;
        int i1 = i0 + 1;
        if (i1 > FW - 1) i1 = FW - 1;
        x0s[i] = i0; x1s[i] = i1; wxs[i] = v - f;
    }
    __syncthreads();

    for (int idx = tid; idx < DFLAT / 4; idx += blockDim.x) {
        int c4 = idx & (FC / 4 - 1);
        int p  = idx >> 7;
        int py = p / POOL;
        int px = p % POOL;

        float m[4] = {-FLT_MAX, -FLT_MAX, -FLT_MAX, -FLT_MAX};
        #pragma unroll
        for (int dy = 0; dy < 2; ++dy) {
            int   iy = 2 * py + dy;
            int   yA = y0s[iy], yB = y1s[iy];
            float wy = wys[iy];
            #pragma unroll
            for (int dx = 0; dx < 2; ++dx) {
                int   ix = 2 * px + dx;
                int   xA = x0s[ix], xB = x1s[ix];
                float wx = wxs[ix];
                float4 f00 = *(const float4*)&feats[((yA * FW + xA) * FC) + c4 * 4];
                float4 f01 = *(const float4*)&feats[((yA * FW + xB) * FC) + c4 * 4];
                float4 f10 = *(const float4*)&feats[((yB * FW + xA) * FC) + c4 * 4];
                float4 f11 = *(const float4*)&feats[((yB * FW + xB) * FC) + c4 * 4];
                float owx = 1.0f - wx, owy = 1.0f - wy;
                float t, b, v;
                t = f00.x * owx + f01.x * wx; b = f10.x * owx + f11.x * wx;
                v = t * owy + b * wy; m[0] = fmaxf(m[0], v);
                t = f00.y * owx + f01.y * wx; b = f10.y * owx + f11.y * wx;
                v = t * owy + b * wy; m[1] = fmaxf(m[1], v);
                t = f00.z * owx + f01.z * wx; b = f10.z * owx + f11.z * wx;
                v = t * owy + b * wy; m[2] = fmaxf(m[2], v);
                t = f00.w * owx + f01.w * wx; b = f10.w * owx + f11.w * wx;
                v = t * owy + b * wy; m[3] = fmaxf(m[3], v);
            }
        }
        uint2 r;
        r.x = pack_h2(m[0], m[1]);
        r.y = pack_h2(m[2], m[3]);
        *(uint2*)&out[(size_t)n * DFLAT + p * FC + c4 * 4] = r;
    }
}

// ---------------------------------------------------------------------------
// Kernel 2: FP16 HMMA GEMM. Both operands fp16 K-major.
// D = relu(A @ Bt^T + bias); A [M,K], Bt [N,K]. Tiles 128x128x64, 8 warps,
// warp tile 64x32, mma m16n8k16, ldmatrix fragments, 3-stage cp.async.
// ---------------------------------------------------------------------------
#define BM 128
#define BN 128
#define BK 64
#define TSTR 72                           // halfs per tile row (64 + 8 pad)
#define TILE_BYTES (128 * TSTR * 2)       // 18432
#define STAGE_BYTES (2 * TILE_BYTES)      // 36864 (A tile + B tile)
#define NSTAGE 3

__device__ __forceinline__ void gemm_load_tile(
    uint32_t sbase, int slot, int kt, int tid,
    const __half* __restrict__ A, const __half* __restrict__ Bt,
    int bm, int bn, int M, int K) {
    uint32_t sa = sbase + (uint32_t)slot * STAGE_BYTES;
    uint32_t sb = sa + TILE_BYTES;
    int kb = kt * BK;
    // A: 128 rows x 64 halfs = 1024 chunks of 16B (8 halfs)
    #pragma unroll
    for (int i = 0; i < 4; ++i) {
        int c = tid + i * 256;
        int r = c >> 3, ch = c & 7;
        int gm = bm + r;
        if (gm >= M) gm = 0;              // pad rows read row 0; discarded later
        cpasync16(sa + (uint32_t)(r * TSTR + ch * 8) * 2,
                  A + (size_t)gm * K + kb + ch * 8);
    }
    // B: 128 n-rows x 64 halfs = 1024 chunks of 16B
    #pragma unroll
    for (int i = 0; i < 4; ++i) {
        int c = tid + i * 256;
        int r = c >> 3, ch = c & 7;
        cpasync16(sb + (uint32_t)(r * TSTR + ch * 8) * 2,
                  Bt + (size_t)(bn + r) * K + kb + ch * 8);
    }
}

__global__ __launch_bounds__(256, 2)
void gemm_f16_pipe(const __half* __restrict__ A, const __half* __restrict__ Bt,
                   const float* __restrict__ bias,
                   __half* __restrict__ outH, float* __restrict__ outF,
                   int M, int N, int K) {
    extern __shared__ char smem[];
    uint32_t sbase = smem_u32(smem);

    const int tid    = threadIdx.x;
    const int bm     = blockIdx.x * BM;
    const int bn     = blockIdx.y * BN;
    const int warpId = tid >> 5;
    const int lane   = tid & 31;
    const int gid    = lane >> 2;
    const int tig    = lane & 3;
    const int warpM  = (warpId >> 2) * 64;
    const int warpN  = (warpId & 3) * 32;

    // ldmatrix per-lane source coordinates
    const int rowA  = warpM + (lane & 15);          // + mf*16
    const int kofA  = ((lane >> 4) << 3);           // + ks*16
    const int colB  = warpN + (lane & 7) + ((lane >> 4) << 3);   // + j*16
    const int kofB  = (((lane >> 3) & 1) << 3);     // + ks*16

    float acc[4][4][4];
    #pragma unroll
    for (int i = 0; i < 4; ++i)
        #pragma unroll
        for (int j = 0; j < 4; ++j)
            #pragma unroll
            for (int r = 0; r < 4; ++r) acc[i][j][r] = 0.0f;

    const int T = K / BK;

    gemm_load_tile(sbase, 0, 0, tid, A, Bt, bm, bn, M, K);
    asm volatile("cp.async.commit_group;" ::: "memory");
    gemm_load_tile(sbase, 1, 1, tid, A, Bt, bm, bn, M, K);
    asm volatile("cp.async.commit_group;" ::: "memory");

    for (int kt = 0; kt < T; ++kt) {
        asm volatile("cp.async.wait_group 1;" ::: "memory");
        __syncthreads();

        if (kt + 2 < T) {
            gemm_load_tile(sbase, (kt + 2) % NSTAGE, kt + 2, tid, A, Bt, bm, bn, M, K);
        }
        asm volatile("cp.async.commit_group;" ::: "memory");  // may be empty

        uint32_t sa = sbase + (uint32_t)(kt % NSTAGE) * STAGE_BYTES;
        uint32_t sb = sa + TILE_BYTES;

        #pragma unroll
        for (int ks = 0; ks < 4; ++ks) {
            uint32_t af[4][4];
            uint32_t bf[4][2];
            #pragma unroll
            for (int mf = 0; mf < 4; ++mf) {
                uint32_t addr = sa + (uint32_t)((rowA + mf * 16) * TSTR + ks * 16 + kofA) * 2;
                ldsm_x4(af[mf], addr);
            }
            #pragma unroll
            for (int j = 0; j < 2; ++j) {
                uint32_t r4[4];
                uint32_t addr = sb + (uint32_t)((colB + j * 16) * TSTR + ks * 16 + kofB) * 2;
                ldsm_x4(r4, addr);
                bf[j * 2][0]     = r4[0];
                bf[j * 2][1]     = r4[1];
                bf[j * 2 + 1][0] = r4[2];
                bf[j * 2 + 1][1] = r4[3];
            }
            #pragma unroll
            for (int mf = 0; mf < 4; ++mf)
                #pragma unroll
                for (int nf = 0; nf < 4; ++nf)
                    mma_f16(acc[mf][nf], af[mf], bf[nf]);
        }
    }

    // ---- epilogue: bias + relu; store fp16 (GEMM1) or fp32 (GEMM2) ----
    #pragma unroll
    for (int mf = 0; mf < 4; ++mf) {
        #pragma unroll
        for (int nf = 0; nf < 4; ++nf) {
            int row0 = bm + warpM + mf * 16 + gid;
            int col0 = bn + warpN + nf * 8 + tig * 2;
            float bv0 = bias[col0];
            float bv1 = bias[col0 + 1];
            if (row0 < M) {
                float v0 = fmaxf(acc[mf][nf][0] + bv0, 0.f);
                float v1 = fmaxf(acc[mf][nf][1] + bv1, 0.f);
                if (outH) *(uint32_t*)&outH[(size_t)row0 * N + col0] = pack_h2(v0, v1);
                else {
                    outF[(size_t)row0 * N + col0]     = v0;
                    outF[(size_t)row0 * N + col0 + 1] = v1;
                }
            }
            if (row0 + 8 < M) {
                float v2 = fmaxf(acc[mf][nf][2] + bv0, 0.f);
                float v3 = fmaxf(acc[mf][nf][3] + bv1, 0.f);
                if (outH) *(uint32_t*)&outH[(size_t)(row0 + 8) * N + col0] = pack_h2(v2, v3);
                else {
                    outF[(size_t)(row0 + 8) * N + col0]     = v2;
                    outF[(size_t)(row0 + 8) * N + col0 + 1] = v3;
                }
            }
        }
    }
}

// ---------------------------------------------------------------------------
// Kernel 3a: heads split-K partial sums (NSPLIT=32, KCH=128).
// ---------------------------------------------------------------------------
__global__ void heads_partial_kernel(const float* __restrict__ X,
                                     const float* __restrict__ Wc,
                                     const float* __restrict__ Wr,
                                     float* __restrict__ part) {
    __shared__ float Xs[8 * 128];
    const int tid   = threadIdx.x;
    const int m0    = blockIdx.x * 8;
    const int ks    = blockIdx.y;
    const int kbase = ks * KCH;
    const int nIdx  = tid & 127;
    const int half  = tid >> 7;
    const bool active = (nIdx < NOUT);

    float acc0 = 0.f, acc1 = 0.f, acc2 = 0.f, acc3 = 0.f;

    for (int kc = kbase; kc < kbase + KCH; kc += 128) {
        #pragma unroll
        for (int i = 0; i < 4; ++i) {
            int idx = tid + i * 256;
            int r = idx >> 7, c = idx & 127;
            Xs[idx] = X[(size_t)(m0 + r) * DH + kc + c];
        }
        __syncthreads();

        #pragma unroll 4
        for (int kk = 0; kk < 128; kk += 4) {
            float w0 = 0.f, w1 = 0.f, w2 = 0.f, w3 = 0.f;
            if (active) {
                if (nIdx < NCLS) {
                    w0 = Wc[(size_t)(kc + kk + 0) * NCLS + nIdx];
                    w1 = Wc[(size_t)(kc + kk + 1) * NCLS + nIdx];
                    w2 = Wc[(size_t)(kc + kk + 2) * NCLS + nIdx];
                    w3 = Wc[(size_t)(kc + kk + 3) * NCLS + nIdx];
                } else {
                    int nr = nIdx - NCLS;
                    w0 = Wr[(size_t)(kc + kk + 0) * NREG + nr];
                    w1 = Wr[(size_t)(kc + kk + 1) * NREG + nr];
                    w2 = Wr[(size_t)(kc + kk + 2) * NREG + nr];
                    w3 = Wr[(size_t)(kc + kk + 3) * NREG + nr];
                }
            }
            {
                float4 x0 = *(const float4*)&Xs[(half * 4 + 0) * 128 + kk];
                float4 x1 = *(const float4*)&Xs[(half * 4 + 1) * 128 + kk];
                float4 x2 = *(const float4*)&Xs[(half * 4 + 2) * 128 + kk];
                float4 x3 = *(const float4*)&Xs[(half * 4 + 3) * 128 + kk];
                acc0 += x0.x * w0 + x0.y * w1 + x0.z * w2 + x0.w * w3;
                acc1 += x1.x * w0 + x1.y * w1 + x1.z * w2 + x1.w * w3;
                acc2 += x2.x * w0 + x2.y * w1 + x2.z * w2 + x2.w * w3;
                acc3 += x3.x * w0 + x3.y * w1 + x3.z * w2 + x3.w * w3;
            }
        }
        __syncthreads();
    }

    if (active) {
        float accs[4] = {acc0, acc1, acc2, acc3};
        #pragma unroll
        for (int j = 0; j < 4; ++j) {
            int m = m0 + half * 4 + j;
            part[((size_t)ks * NROI + m) * NPAD + nIdx] = accs[j];
        }
    }
}

// ---------------------------------------------------------------------------
// Kernel 3b: reduce partials + bias
// ---------------------------------------------------------------------------
__global__ void heads_reduce_kernel(const float* __restrict__ part,
                                    const float* __restrict__ bc,
                                    const float* __restrict__ br,
                                    float* __restrict__ cls_logits,
                                    float* __restrict__ reg_out) {
    int idx = blockIdx.x * blockDim.x + threadIdx.x;
    if (idx >= NROI * NPAD) return;
    int m = idx / NPAD;
    int n = idx % NPAD;
    if (n >= NOUT) return;

    float s = 0.f;
    #pragma unroll
    for (int ks = 0; ks < NSPLIT; ++ks)
        s += part[((size_t)ks * NROI + m) * NPAD + n];

    if (n < NCLS) cls_logits[m * NCLS + n] = s + bc[n];
    else          reg_out[m * NREG + (n - NCLS)] = s + br[n - NCLS];
}

// ---------------------------------------------------------------------------
// Kernel 4: softmax over 21 classes
// ---------------------------------------------------------------------------
__global__ void softmax21_kernel(const float* __restrict__ logits,
                                 float* __restrict__ out) {
    int m = blockIdx.x * blockDim.x + threadIdx.x;
    if (m >= NROI) return;
    float v[NCLS];
    float mx = -FLT_MAX;
    #pragma unroll
    for (int j = 0; j < NCLS; ++j) {
        v[j] = logits[m * NCLS + j];
        mx = fmaxf(mx, v[j]);
    }
    float s = 0.f;
    #pragma unroll
    for (int j = 0; j < NCLS; ++j) {
        v[j] = expf(v[j] - mx);
        s += v[j];
    }
    float inv = 1.0f / s;
    #pragma unroll
    for (int j = 0; j < NCLS; ++j) out[m * NCLS + j] = v[j] * inv;
}

// ---------------------------------------------------------------------------
// Launch
// ---------------------------------------------------------------------------
extern "C" void kernel_launch(void* const* d_in, const int* in_sizes, int n_in,
                              void* d_out, int out_size) {
    const float* feats = (const float*)d_in[0];
    const float* props = (const float*)d_in[1];
    const float* W1    = (const float*)d_in[2];
    const float* b1    = (const float*)d_in[3];
    const float* W2    = (const float*)d_in[4];
    const float* b2    = (const float*)d_in[5];
    const float* Wc    = (const float*)d_in[6];
    const float* bc    = (const float*)d_in[7];
    const float* Wr    = (const float*)d_in[8];
    const float* br    = (const float*)d_in[9];
    float* out = (float*)d_out;

    __half *pooled, *W1t, *W2t, *h1;
    float *h2, *cls, *part;
    cudaGetSymbolAddress((void**)&pooled, g_pooled);
    cudaGetSymbolAddress((void**)&W1t, g_W1t);
    cudaGetSymbolAddress((void**)&W2t, g_W2t);
    cudaGetSymbolAddress((void**)&h1, g_h1);
    cudaGetSymbolAddress((void**)&h2, g_h2);
    cudaGetSymbolAddress((void**)&cls, g_cls);
    cudaGetSymbolAddress((void**)&part, g_part);

    const int smemsz = NSTAGE * STAGE_BYTES;  // 110592 B
    cudaFuncSetAttribute(gemm_f16_pipe, cudaFuncAttributeMaxDynamicSharedMemorySize, smemsz);

    // 0,1: weight transpose+convert -> fp16 [N,K]
    transpose_f16_kernel<<<dim3(DH / 32, DFLAT / 32), dim3(32, 8)>>>(W1, W1t, DFLAT, DH);
    transpose_f16_kernel<<<dim3(DH / 32, DH / 32),    dim3(32, 8)>>>(W2, W2t, DH, DH);

    // 2: ROI pool -> fp16 A
    roi_pool_kernel<<<NROI, 256>>>(feats, props, pooled);

    // 3: GEMM1 (lands on the profiler's capture slot)
    gemm_f16_pipe<<<dim3((NROI + BM - 1) / BM, DH / BN), 256, smemsz>>>(
        pooled, W1t, b1, h1, (float*)0, NROI, DH, DFLAT);

    // 4: GEMM2
    gemm_f16_pipe<<<dim3((NROI + BM - 1) / BM, DH / BN), 256, smemsz>>>(
        h1, W2t, b2, (__half*)0, h2, NROI, DH, DH);

    heads_partial_kernel<<<dim3(NROI / 8, NSPLIT), 256>>>(h2, Wc, Wr, part);

    heads_reduce_kernel<<<(NROI * NPAD + 255) / 256, 256>>>(
        part, bc, br, cls, out + NROI * NCLS);

    softmax21_kernel<<<4, 256>>>(cls, out);
}